// round 12
// baseline (speedup 1.0000x reference)
#include <cuda_runtime.h>
#include <cuda_bf16.h>
#include <cstdint>

// Problem constants
#define NN   50000
#define EE   800000
#define HH   4
#define CC   64
#define DD   4
#define FOUT 256   // H*C
#define NB2  ((NN + 255) / 256)   // 196 blocks of 256

// ---------------- scratch (device globals; no allocation allowed) ----------
__device__ __align__(16) float g_h[(size_t)NN * FOUT];    // message features [N,256]
__device__ __align__(16) float g_x2[(size_t)NN * CC];     // layer-1 output  [N,64]
__device__ __align__(16) float g_asrc[NN * HH];
__device__ __align__(16) float g_adst[NN * HH];
__device__ __align__(16) float g_vsrc1[128 * HH];
__device__ __align__(16) float g_vdst1[128 * HH];
__device__ __align__(16) float g_vsrc2[64 * HH];
__device__ __align__(16) float g_vdst2[64 * HH];
__device__ int g_count[NN];
__device__ int g_off[NN];
__device__ int g_rowptr[NN + 1];
__device__ int g_csr[EE];
__device__ int g_is64;
__device__ int g_bsum[256];
__device__ int g_bpre[256];

__device__ __forceinline__ float lrelu(float v, float s) { return v >= 0.f ? v : s * v; }

// 32-bit edge-index load: element i of the edge array is the low word at
// 2*i (int64 little-endian) or word i (int32). Values < 50000 fit in 32 bits.
__device__ __forceinline__ int edge_lo(const int* ei_words, size_t i, int is64) {
    return ei_words[is64 ? 2 * i : i];
}

// packed f32x2 helpers (sm_103a)
__device__ __forceinline__ unsigned long long pack2(float lo, float hi) {
    unsigned long long r;
    asm("mov.b64 %0, {%1, %2};" : "=l"(r) : "f"(lo), "f"(hi));
    return r;
}
__device__ __forceinline__ void ffma2(unsigned long long& d, unsigned long long a,
                                      unsigned long long b) {
    asm("fma.rn.f32x2 %0, %1, %2, %0;" : "+l"(d) : "l"(a), "l"(b));
}
__device__ __forceinline__ void mul2(unsigned long long& d, unsigned long long a) {
    asm("mul.rn.f32x2 %0, %0, %1;" : "+l"(d) : "l"(a));
}
__device__ __forceinline__ float lo2(unsigned long long v) {
    float a, b; asm("mov.b64 {%0, %1}, %2;" : "=f"(a), "=f"(b) : "l"(v)); return a;
}
__device__ __forceinline__ float hi2(unsigned long long v) {
    float a, b; asm("mov.b64 {%0, %1}, %2;" : "=f"(a), "=f"(b) : "l"(v)); return b;
}

// tf32 helpers
__device__ __forceinline__ uint32_t tf32r(float f) {
    uint32_t r;
    asm("cvt.rna.tf32.f32 %0, %1;" : "=r"(r) : "f"(f));
    return r;
}
__device__ __forceinline__ void mma_tf32(float& d0, float& d1, float& d2, float& d3,
                                         uint32_t a0, uint32_t a1, uint32_t a2, uint32_t a3,
                                         uint32_t b0, uint32_t b1) {
    asm("mma.sync.aligned.m16n8k8.row.col.f32.tf32.tf32.f32 "
        "{%0,%1,%2,%3}, {%4,%5,%6,%7}, {%8,%9}, {%0,%1,%2,%3};"
        : "+f"(d0), "+f"(d1), "+f"(d2), "+f"(d3)
        : "r"(a0), "r"(a1), "r"(a2), "r"(a3), "r"(b0), "r"(b1));
}

// ---------------- fused prep: zero counts + dtype detect + both combines ---
__global__ __launch_bounds__(256) void k_prep(const int* ei_words,
                                              const float* __restrict__ A1,
                                              const float* __restrict__ as1,
                                              const float* __restrict__ ad1,
                                              const float* __restrict__ A2,
                                              const float* __restrict__ as2,
                                              const float* __restrict__ ad2) {
    int i = blockIdx.x * 256 + threadIdx.x;
    if (i < NN) g_count[i] = 0;
    if (i == 0) {
        int nz = 0;
        for (int j = 0; j < 64; j++)
            if (ei_words[2 * j + 1] != 0) nz++;
        g_is64 = (nz == 0) ? 1 : 0;
    }
    if (i < 128 * HH) {
        int f = i >> 2, h = i & 3;
        float s1 = 0.f, s2 = 0.f;
        #pragma unroll
        for (int d = 0; d < DD; d++) {
            float a = A1[f * (HH * DD) + h * DD + d];
            s1 += a * as1[h * DD + d];
            s2 += a * ad1[h * DD + d];
        }
        g_vsrc1[f * HH + h] = s1;
        g_vdst1[f * HH + h] = s2;
    }
    if (i < 64 * HH) {
        int f = i >> 2, h = i & 3;
        float s1 = 0.f, s2 = 0.f;
        #pragma unroll
        for (int d = 0; d < DD; d++) {
            float a = A2[f * (HH * DD) + h * DD + d];
            s1 += a * as2[h * DD + d];
            s2 += a * ad2[h * DD + d];
        }
        g_vsrc2[f * HH + h] = s1;
        g_vdst2[f * HH + h] = s2;
    }
}

__global__ void k_hist(const int* ei_words) {
    int e = blockIdx.x * blockDim.x + threadIdx.x;
    if (e >= EE) return;
    int dst = edge_lo(ei_words, (size_t)EE + e, g_is64);
    atomicAdd(&g_count[dst], 1);
}

// ---- parallel scan: blocksum -> scan of partials -> per-block writeout ----
__global__ __launch_bounds__(256) void k_blocksum() {
    __shared__ int sh[8];
    int i = blockIdx.x * 256 + threadIdx.x;
    int v = (i < NN) ? g_count[i] : 0;
    #pragma unroll
    for (int o = 16; o; o >>= 1) v += __shfl_xor_sync(0xffffffffu, v, o);
    if ((threadIdx.x & 31) == 0) sh[threadIdx.x >> 5] = v;
    __syncthreads();
    if (threadIdx.x == 0) {
        int s = 0;
        #pragma unroll
        for (int j = 0; j < 8; j++) s += sh[j];
        g_bsum[blockIdx.x] = s;
    }
}

__global__ __launch_bounds__(256) void k_scanb(int nb) {
    __shared__ int sh[256];
    int t = threadIdx.x;
    int v = (t < nb) ? g_bsum[t] : 0;
    sh[t] = v;
    __syncthreads();
    for (int o = 1; o < 256; o <<= 1) {
        int u = (t >= o) ? sh[t - o] : 0;
        __syncthreads();
        sh[t] += u;
        __syncthreads();
    }
    if (t < nb) g_bpre[t] = sh[t] - v;  // exclusive
}

__global__ __launch_bounds__(256) void k_writeoff() {
    __shared__ int wpre[8];
    int t = threadIdx.x;
    int lane = t & 31, w = t >> 5;
    int i = blockIdx.x * 256 + t;
    int c = (i < NN) ? g_count[i] : 0;
    int v = c;
    #pragma unroll
    for (int o = 1; o < 32; o <<= 1) {
        int u = __shfl_up_sync(0xffffffffu, v, o);
        if (lane >= o) v += u;
    }
    if (lane == 31) wpre[w] = v;
    __syncthreads();
    if (t == 0) {
        int run = 0;
        #pragma unroll
        for (int j = 0; j < 8; j++) { int tmp = wpre[j]; wpre[j] = run; run += tmp; }
    }
    __syncthreads();
    int excl = v - c + wpre[w] + g_bpre[blockIdx.x];
    if (i < NN) {
        g_rowptr[i] = excl;
        g_off[i] = excl;
        if (i == NN - 1) g_rowptr[NN] = excl + c;
    }
}

__global__ void k_scatter(const int* ei_words) {
    int e = blockIdx.x * blockDim.x + threadIdx.x;
    if (e >= EE) return;
    int is64 = g_is64;
    int src = edge_lo(ei_words, (size_t)e, is64);
    int dst = edge_lo(ei_words, (size_t)EE + e, is64);
    int pos = atomicAdd(&g_off[dst], 1);
    g_csr[pos] = src;
}

// ---------------- tf32 tensor-core GEMM: whole W in smem, barrier-free -----
// 256 thr = 8 warps; block tile 64 rows x 256 cols; warp tile 32 x 64.
// ALL of W lives in dynamic smem (FIN x 264-stride); one __syncthreads total,
// then the K loop streams LDS->MMA with no synchronization.
// xs stride = FIN+4 (== 4 mod 32): A-frag LDS conflict-free.
// ws stride = 264    (== 8 mod 32): B-frag LDS conflict-free
//   (bank = 8*lk + l4 + 8*j mod 32 covers 0..31 across the warp).
template <int FIN>
__global__ __launch_bounds__(256) void k_gemm(const float* __restrict__ x,
                                              const float* __restrict__ W,
                                              float* __restrict__ hout,
                                              const float* __restrict__ vs,
                                              const float* __restrict__ vd,
                                              float* __restrict__ asrc,
                                              float* __restrict__ adst, int n) {
    constexpr int XST = FIN + 4;
    constexpr int WST = 264;
    extern __shared__ float smem[];
    float* xs = smem;                 // 64 * XST
    float* ws = smem + 64 * XST;      // FIN * WST
    int tid = threadIdx.x;
    int lane = tid & 31;
    int w = tid >> 5;
    int row0 = blockIdx.x * 64;
    int mrow = (w >> 2) * 32;
    int ncol = (w & 3) * 64;
    int l4 = lane >> 2;       // 0..7
    int lk = lane & 3;        // 0..3

    // load + tf32-round x tile
    for (int idx = tid; idx < 64 * FIN; idx += 256) {
        int r = idx / FIN, k = idx - r * FIN;
        int row = row0 + r;
        float v = (row < n) ? x[(size_t)row * FIN + k] : 0.f;
        xs[r * XST + k] = __uint_as_float(tf32r(v));
    }
    // load + tf32-round ALL of W (consecutive tids -> consecutive cols: no conflicts)
    for (int idx = tid; idx < FIN * FOUT; idx += 256) {
        int k = idx >> 8, c = idx & 255;
        ws[k * WST + c] = __uint_as_float(tf32r(W[idx]));
    }
    __syncthreads();   // the only barrier

    float d[2][8][4];
    #pragma unroll
    for (int t = 0; t < 2; t++)
        #pragma unroll
        for (int j = 0; j < 8; j++)
            #pragma unroll
            for (int q = 0; q < 4; q++) d[t][j][q] = 0.f;

    #pragma unroll 4
    for (int kc = 0; kc < FIN; kc += 8) {
        // B fragments (shared by both m-tiles)
        uint32_t b0[8], b1[8];
        #pragma unroll
        for (int j = 0; j < 8; j++) {
            int col = ncol + j * 8 + l4;
            b0[j] = __float_as_uint(ws[(kc + lk) * WST + col]);
            b1[j] = __float_as_uint(ws[(kc + lk + 4) * WST + col]);
        }
        #pragma unroll
        for (int t = 0; t < 2; t++) {
            int rb = mrow + t * 16 + l4;
            int kk = kc + lk;
            uint32_t a0 = __float_as_uint(xs[rb * XST + kk]);
            uint32_t a1 = __float_as_uint(xs[(rb + 8) * XST + kk]);
            uint32_t a2 = __float_as_uint(xs[rb * XST + kk + 4]);
            uint32_t a3 = __float_as_uint(xs[(rb + 8) * XST + kk + 4]);
            #pragma unroll
            for (int j = 0; j < 8; j++)
                mma_tf32(d[t][j][0], d[t][j][1], d[t][j][2], d[t][j][3],
                         a0, a1, a2, a3, b0[j], b1[j]);
        }
    }

    // store D
    #pragma unroll
    for (int t = 0; t < 2; t++) {
        int r0 = row0 + mrow + t * 16 + l4;
        #pragma unroll
        for (int j = 0; j < 8; j++) {
            int c = ncol + j * 8 + lk * 2;
            if (r0 < n)
                *(float2*)&hout[(size_t)r0 * FOUT + c] = make_float2(d[t][j][0], d[t][j][1]);
            if (r0 + 8 < n)
                *(float2*)&hout[(size_t)(r0 + 8) * FOUT + c] = make_float2(d[t][j][2], d[t][j][3]);
        }
    }

    // alpha: 256 threads = 64 rows x 4 heads (tf32-rounded x)
    {
        int r = tid >> 2, h = tid & 3;
        int row = row0 + r;
        if (row < n) {
            float s1 = 0.f, s2 = 0.f;
            #pragma unroll 8
            for (int k = 0; k < FIN; k++) {
                float xv = xs[r * XST + k];
                s1 = fmaf(xv, vs[k * HH + h], s1);
                s2 = fmaf(xv, vd[k * HH + h], s2);
            }
            asrc[row * HH + h] = s1;
            adst[row * HH + h] = s2;
        }
    }
}

// ---------------- per-dst-node softmax + weighted aggregation (1 warp/node)
// Softmax without max subtraction (|e| bounded ~0.5 by construction).
// Lane l owns channels [8l, 8l+8) (h = l>>3); head-average folded via
// butterfly shfl at the end.
__global__ __launch_bounds__(256) void k_aggr(const float* __restrict__ hf,
                                              const float* __restrict__ asrc,
                                              const float* __restrict__ adst,
                                              const float* __restrict__ bias,
                                              float* __restrict__ out, int n) {
    __shared__ float4 wbuf[8][32];
    __shared__ int    sbuf[8][32];
    int wid = threadIdx.x >> 5;
    int lane = threadIdx.x & 31;
    int node = (blockIdx.x * blockDim.x + threadIdx.x) >> 5;
    if (node >= n) return;

    int base = g_rowptr[node];
    int deg = g_rowptr[node + 1] - base;
    int h = lane >> 3;

    float4 ad = *(const float4*)(adst + (size_t)node * 4);

    float d0 = 0.f, d1 = 0.f, d2 = 0.f, d3 = 0.f;
    unsigned long long acc[4] = {0ull, 0ull, 0ull, 0ull};
    const float* hlane = hf + lane * 8;

    for (int ib = 0; ib < deg; ib += 32) {
        int rem = min(32, deg - ib);
        {
            int sl = 0;
            float w0 = 0.f, w1 = 0.f, w2 = 0.f, w3 = 0.f;
            if (lane < rem) {
                sl = g_csr[base + ib + lane];
                float4 as = *(const float4*)(asrc + (size_t)sl * 4);
                w0 = __expf(lrelu(as.x + ad.x, 0.2f));
                w1 = __expf(lrelu(as.y + ad.y, 0.2f));
                w2 = __expf(lrelu(as.z + ad.z, 0.2f));
                w3 = __expf(lrelu(as.w + ad.w, 0.2f));
                d0 += w0; d1 += w1; d2 += w2; d3 += w3;
            }
            sbuf[wid][lane] = sl;
            wbuf[wid][lane] = make_float4(w0, w1, w2, w3);
        }
        __syncwarp();
        for (int j = 0; j < rem; j++) {
            int s = sbuf[wid][j];                 // LDS broadcast
            float4 wv = wbuf[wid][j];             // LDS.128 broadcast
            float w = (h == 0) ? wv.x : (h == 1) ? wv.y : (h == 2) ? wv.z : wv.w;
            unsigned long long w2p = pack2(w, w);
            const ulonglong2* hp = (const ulonglong2*)(hlane + (size_t)s * FOUT);
            ulonglong2 hA = hp[0];
            ulonglong2 hB = hp[1];
            ffma2(acc[0], w2p, hA.x);
            ffma2(acc[1], w2p, hA.y);
            ffma2(acc[2], w2p, hB.x);
            ffma2(acc[3], w2p, hB.y);
        }
        __syncwarp();
    }

    #pragma unroll
    for (int o = 16; o; o >>= 1) {
        d0 += __shfl_xor_sync(0xffffffffu, d0, o);
        d1 += __shfl_xor_sync(0xffffffffu, d1, o);
        d2 += __shfl_xor_sync(0xffffffffu, d2, o);
        d3 += __shfl_xor_sync(0xffffffffu, d3, o);
    }
    float i0 = d0 > 0.f ? 0.25f / d0 : 0.f;
    float i1 = d1 > 0.f ? 0.25f / d1 : 0.f;
    float i2 = d2 > 0.f ? 0.25f / d2 : 0.f;
    float i3 = d3 > 0.f ? 0.25f / d3 : 0.f;
    float inv = (h == 0) ? i0 : (h == 1) ? i1 : (h == 2) ? i2 : i3;
    unsigned long long inv2 = pack2(inv, inv);
    #pragma unroll
    for (int j = 0; j < 4; j++) mul2(acc[j], inv2);

    float v[8];
    #pragma unroll
    for (int j = 0; j < 4; j++) { v[2 * j] = lo2(acc[j]); v[2 * j + 1] = hi2(acc[j]); }
    #pragma unroll
    for (int j = 0; j < 8; j++) {
        v[j] += __shfl_xor_sync(0xffffffffu, v[j], 8);
        v[j] += __shfl_xor_sync(0xffffffffu, v[j], 16);
    }

    if (lane < 8) {
        const float4* bp = (const float4*)(bias + lane * 8);
        float4 bA = bp[0], bB = bp[1];
        float4 oA = make_float4(lrelu(v[0] + bA.x, 0.1f), lrelu(v[1] + bA.y, 0.1f),
                                lrelu(v[2] + bA.z, 0.1f), lrelu(v[3] + bA.w, 0.1f));
        float4 oB = make_float4(lrelu(v[4] + bB.x, 0.1f), lrelu(v[5] + bB.y, 0.1f),
                                lrelu(v[6] + bB.z, 0.1f), lrelu(v[7] + bB.w, 0.1f));
        float4* op = (float4*)(out + (size_t)node * CC + lane * 8);
        op[0] = oA;
        op[1] = oB;
    }
}

// ---------------------------------------------------------------------------
extern "C" void kernel_launch(void* const* d_in, const int* in_sizes, int n_in,
                              void* d_out, int out_size) {
    const float* x        = (const float*)d_in[0];
    const int*   ei       = (const int*)d_in[1];
    const float* W1       = (const float*)d_in[2];
    const float* A1       = (const float*)d_in[3];
    const float* att_src1 = (const float*)d_in[4];
    const float* att_dst1 = (const float*)d_in[5];
    const float* b1       = (const float*)d_in[6];
    const float* W2       = (const float*)d_in[7];
    const float* A2       = (const float*)d_in[8];
    const float* att_src2 = (const float*)d_in[9];
    const float* att_dst2 = (const float*)d_in[10];
    const float* b2       = (const float*)d_in[11];
    float* out = (float*)d_out;

    const int n = NN;
    const int eb = (EE + 255) / 256;

    // dynamic smem sizes
    const int SM1 = (64 * (128 + 4) + 128 * 264) * 4;   // 168,960 B
    const int SM2 = (64 * (64 + 4) + 64 * 264) * 4;     //  84,992 B
    static bool attr_set = false;
    if (!attr_set) {
        cudaFuncSetAttribute(k_gemm<128>, cudaFuncAttributeMaxDynamicSharedMemorySize, SM1);
        cudaFuncSetAttribute(k_gemm<64>,  cudaFuncAttributeMaxDynamicSharedMemorySize, SM2);
        attr_set = true;
    }

    float *p_h, *p_x2, *p_asrc, *p_adst, *p_vs1, *p_vd1, *p_vs2, *p_vd2;
    cudaGetSymbolAddress((void**)&p_h, g_h);
    cudaGetSymbolAddress((void**)&p_x2, g_x2);
    cudaGetSymbolAddress((void**)&p_asrc, g_asrc);
    cudaGetSymbolAddress((void**)&p_adst, g_adst);
    cudaGetSymbolAddress((void**)&p_vs1, g_vsrc1);
    cudaGetSymbolAddress((void**)&p_vd1, g_vdst1);
    cudaGetSymbolAddress((void**)&p_vs2, g_vsrc2);
    cudaGetSymbolAddress((void**)&p_vd2, g_vdst2);

    // #1 prep (zero counts + detect + both combines)
    k_prep<<<NB2, 256>>>(ei, A1, att_src1, att_dst1, A2, att_src2, att_dst2);
    // #2-#3 CSR start
    k_hist<<<eb, 256>>>(ei);
    k_blocksum<<<NB2, 256>>>();
    // #4 gemm1 (profiler captures launch #4; independent of CSR)
    k_gemm<128><<<(n + 63) / 64, 256, SM1>>>(x, W1, p_h, p_vs1, p_vd1, p_asrc, p_adst, n);
    // #5-#7 CSR finish
    k_scanb<<<1, 256>>>(NB2);
    k_writeoff<<<NB2, 256>>>();
    k_scatter<<<eb, 256>>>(ei);
    // #8 layer-1 aggregation
    k_aggr<<<(n * 32 + 255) / 256, 256>>>(p_h, p_asrc, p_adst, b1, p_x2, n);
    // #9-#10 layer 2
    k_gemm<64><<<(n + 63) / 64, 256, SM2>>>(p_x2, W2, p_h, p_vs2, p_vd2, p_asrc, p_adst, n);
    k_aggr<<<(n * 32 + 255) / 256, 256>>>(p_h, p_asrc, p_adst, b2, out, n);
}

// round 13
// speedup vs baseline: 1.4752x; 1.4752x over previous
#include <cuda_runtime.h>
#include <cuda_fp16.h>
#include <cuda_bf16.h>
#include <cstdint>

// Problem constants
#define NN   50000
#define EE   800000
#define HH   4
#define CC   64
#define DD   4
#define FOUT 256   // H*C
#define NB2  ((NN + 255) / 256)   // 196 blocks of 256

// ---------------- scratch (device globals; no allocation allowed) ----------
__device__ __align__(16) __half g_h[(size_t)NN * FOUT];   // h messages, fp16
__device__ __align__(16) float g_x2[(size_t)NN * CC];     // layer-1 output
__device__ __align__(16) float g_asrc[NN * HH];
__device__ __align__(16) float g_adst[NN * HH];
__device__ __align__(16) float g_vsrc1[128 * HH];
__device__ __align__(16) float g_vdst1[128 * HH];
__device__ __align__(16) float g_vsrc2[64 * HH];
__device__ __align__(16) float g_vdst2[64 * HH];
__device__ int g_count[NN];
__device__ int g_off[NN];
__device__ int g_rowptr[NN + 1];
__device__ int g_csr[EE];
__device__ int g_is64;
__device__ int g_bsum[256];
__device__ int g_bpre[256];

__device__ __forceinline__ float lrelu(float v, float s) { return v >= 0.f ? v : s * v; }

// 32-bit edge-index load: element i is the low word at 2*i (int64 LE) or
// word i (int32). Node ids < 50000 always fit in the low 32 bits.
__device__ __forceinline__ int edge_lo(const int* ei_words, size_t i, int is64) {
    return ei_words[is64 ? 2 * i : i];
}

// packed f32x2 helpers (sm_103a)
__device__ __forceinline__ unsigned long long pack2(float lo, float hi) {
    unsigned long long r;
    asm("mov.b64 %0, {%1, %2};" : "=l"(r) : "f"(lo), "f"(hi));
    return r;
}
__device__ __forceinline__ void ffma2(unsigned long long& d, unsigned long long a,
                                      unsigned long long b) {
    asm("fma.rn.f32x2 %0, %1, %2, %0;" : "+l"(d) : "l"(a), "l"(b));
}
__device__ __forceinline__ void mul2(unsigned long long& d, unsigned long long a) {
    asm("mul.rn.f32x2 %0, %0, %1;" : "+l"(d) : "l"(a));
}
__device__ __forceinline__ float lo2(unsigned long long v) {
    float a, b; asm("mov.b64 {%0, %1}, %2;" : "=f"(a), "=f"(b) : "l"(v)); return a;
}
__device__ __forceinline__ float hi2(unsigned long long v) {
    float a, b; asm("mov.b64 {%0, %1}, %2;" : "=f"(a), "=f"(b) : "l"(v)); return b;
}
// half2 word -> packed f32x2
__device__ __forceinline__ unsigned long long h2f2(uint32_t u) {
    __half2 h = *reinterpret_cast<__half2*>(&u);
    float2 f = __half22float2(h);
    return pack2(f.x, f.y);
}

// tf32 helpers
__device__ __forceinline__ uint32_t tf32r(float f) {
    uint32_t r;
    asm("cvt.rna.tf32.f32 %0, %1;" : "=r"(r) : "f"(f));
    return r;
}
__device__ __forceinline__ void mma_tf32(float& d0, float& d1, float& d2, float& d3,
                                         uint32_t a0, uint32_t a1, uint32_t a2, uint32_t a3,
                                         uint32_t b0, uint32_t b1) {
    asm("mma.sync.aligned.m16n8k8.row.col.f32.tf32.tf32.f32 "
        "{%0,%1,%2,%3}, {%4,%5,%6,%7}, {%8,%9}, {%0,%1,%2,%3};"
        : "+f"(d0), "+f"(d1), "+f"(d2), "+f"(d3)
        : "r"(a0), "r"(a1), "r"(a2), "r"(a3), "r"(b0), "r"(b1));
}
// pack (lo=a, hi=b) into fp16x2 word
__device__ __forceinline__ uint32_t hpack(float a, float b) {
    uint32_t r;
    asm("cvt.rn.f16x2.f32 %0, %1, %2;" : "=r"(r) : "f"(b), "f"(a));
    return r;
}

// ---------------- fused prep: zero counts + dtype detect + both combines ---
__global__ __launch_bounds__(256) void k_prep(const int* ei_words,
                                              const float* __restrict__ A1,
                                              const float* __restrict__ as1,
                                              const float* __restrict__ ad1,
                                              const float* __restrict__ A2,
                                              const float* __restrict__ as2,
                                              const float* __restrict__ ad2) {
    int i = blockIdx.x * 256 + threadIdx.x;
    if (i < NN) g_count[i] = 0;
    if (i == 0) {
        int nz = 0;
        for (int j = 0; j < 64; j++)
            if (ei_words[2 * j + 1] != 0) nz++;
        g_is64 = (nz == 0) ? 1 : 0;
    }
    if (i < 128 * HH) {
        int f = i >> 2, h = i & 3;
        float s1 = 0.f, s2 = 0.f;
        #pragma unroll
        for (int d = 0; d < DD; d++) {
            float a = A1[f * (HH * DD) + h * DD + d];
            s1 += a * as1[h * DD + d];
            s2 += a * ad1[h * DD + d];
        }
        g_vsrc1[f * HH + h] = s1;
        g_vdst1[f * HH + h] = s2;
    }
    if (i < 64 * HH) {
        int f = i >> 2, h = i & 3;
        float s1 = 0.f, s2 = 0.f;
        #pragma unroll
        for (int d = 0; d < DD; d++) {
            float a = A2[f * (HH * DD) + h * DD + d];
            s1 += a * as2[h * DD + d];
            s2 += a * ad2[h * DD + d];
        }
        g_vsrc2[f * HH + h] = s1;
        g_vdst2[f * HH + h] = s2;
    }
}

__global__ void k_hist(const int* ei_words) {
    int e = blockIdx.x * blockDim.x + threadIdx.x;
    if (e >= EE) return;
    int dst = edge_lo(ei_words, (size_t)EE + e, g_is64);
    atomicAdd(&g_count[dst], 1);
}

// ---- parallel scan: blocksum -> scan of partials -> per-block writeout ----
__global__ __launch_bounds__(256) void k_blocksum() {
    __shared__ int sh[8];
    int i = blockIdx.x * 256 + threadIdx.x;
    int v = (i < NN) ? g_count[i] : 0;
    #pragma unroll
    for (int o = 16; o; o >>= 1) v += __shfl_xor_sync(0xffffffffu, v, o);
    if ((threadIdx.x & 31) == 0) sh[threadIdx.x >> 5] = v;
    __syncthreads();
    if (threadIdx.x == 0) {
        int s = 0;
        #pragma unroll
        for (int j = 0; j < 8; j++) s += sh[j];
        g_bsum[blockIdx.x] = s;
    }
}

__global__ __launch_bounds__(256) void k_scanb(int nb) {
    __shared__ int sh[256];
    int t = threadIdx.x;
    int v = (t < nb) ? g_bsum[t] : 0;
    sh[t] = v;
    __syncthreads();
    for (int o = 1; o < 256; o <<= 1) {
        int u = (t >= o) ? sh[t - o] : 0;
        __syncthreads();
        sh[t] += u;
        __syncthreads();
    }
    if (t < nb) g_bpre[t] = sh[t] - v;  // exclusive
}

__global__ __launch_bounds__(256) void k_writeoff() {
    __shared__ int wpre[8];
    int t = threadIdx.x;
    int lane = t & 31, w = t >> 5;
    int i = blockIdx.x * 256 + t;
    int c = (i < NN) ? g_count[i] : 0;
    int v = c;
    #pragma unroll
    for (int o = 1; o < 32; o <<= 1) {
        int u = __shfl_up_sync(0xffffffffu, v, o);
        if (lane >= o) v += u;
    }
    if (lane == 31) wpre[w] = v;
    __syncthreads();
    if (t == 0) {
        int run = 0;
        #pragma unroll
        for (int j = 0; j < 8; j++) { int tmp = wpre[j]; wpre[j] = run; run += tmp; }
    }
    __syncthreads();
    int excl = v - c + wpre[w] + g_bpre[blockIdx.x];
    if (i < NN) {
        g_rowptr[i] = excl;
        g_off[i] = excl;
        if (i == NN - 1) g_rowptr[NN] = excl + c;
    }
}

__global__ void k_scatter(const int* ei_words) {
    int e = blockIdx.x * blockDim.x + threadIdx.x;
    if (e >= EE) return;
    int is64 = g_is64;
    int src = edge_lo(ei_words, (size_t)e, is64);
    int dst = edge_lo(ei_words, (size_t)EE + e, is64);
    int pos = atomicAdd(&g_off[dst], 1);
    g_csr[pos] = src;
}

// ---------------- tf32 tensor-core GEMM (fat tiles) + W reg prefetch -------
// 256 thr = 8 warps; block tile 64 rows x 256 cols; warp tile 32 x 64.
// fp16 output. xs stride = FIN+4; ws stride = 264 (both conflict-free).
template <int FIN>
__global__ __launch_bounds__(256, 2) void k_gemm(const float* __restrict__ x,
                                                 const float* __restrict__ W,
                                                 __half* __restrict__ hout,
                                                 const float* __restrict__ vs,
                                                 const float* __restrict__ vd,
                                                 float* __restrict__ asrc,
                                                 float* __restrict__ adst, int n) {
    constexpr int XST = FIN + 4;
    constexpr int WST = 264;
    __shared__ float xs[64 * XST];
    __shared__ float ws[8 * WST];
    int tid = threadIdx.x;
    int lane = tid & 31;
    int w = tid >> 5;
    int row0 = blockIdx.x * 64;
    int mrow = (w >> 2) * 32;
    int ncol = (w & 3) * 64;
    int l4 = lane >> 2;       // 0..7
    int lk = lane & 3;        // 0..3

    for (int idx = tid; idx < 64 * FIN; idx += 256) {
        int r = idx / FIN, k = idx - r * FIN;
        int row = row0 + r;
        float v = (row < n) ? x[(size_t)row * FIN + k] : 0.f;
        xs[r * XST + k] = __uint_as_float(tf32r(v));
    }

    // prefetch chunk 0 of W
    float wreg[8];
    #pragma unroll
    for (int i = 0; i < 8; i++) wreg[i] = W[(size_t)i * FOUT + tid];

    float d[2][8][4];
    #pragma unroll
    for (int t = 0; t < 2; t++)
        #pragma unroll
        for (int j = 0; j < 8; j++)
            #pragma unroll
            for (int q = 0; q < 4; q++) d[t][j][q] = 0.f;

    for (int kc = 0; kc < FIN; kc += 8) {
        __syncthreads();
        #pragma unroll
        for (int i = 0; i < 8; i++)
            ws[i * WST + tid] = __uint_as_float(tf32r(wreg[i]));
        __syncthreads();

        if (kc + 8 < FIN) {
            #pragma unroll
            for (int i = 0; i < 8; i++)
                wreg[i] = W[(size_t)(kc + 8 + i) * FOUT + tid];
        }

        uint32_t b0[8], b1[8];
        #pragma unroll
        for (int j = 0; j < 8; j++) {
            int col = ncol + j * 8 + l4;
            b0[j] = __float_as_uint(ws[lk * WST + col]);
            b1[j] = __float_as_uint(ws[(lk + 4) * WST + col]);
        }
        #pragma unroll
        for (int t = 0; t < 2; t++) {
            int rb = mrow + t * 16 + l4;
            int kk = kc + lk;
            uint32_t a0 = __float_as_uint(xs[rb * XST + kk]);
            uint32_t a1 = __float_as_uint(xs[(rb + 8) * XST + kk]);
            uint32_t a2 = __float_as_uint(xs[rb * XST + kk + 4]);
            uint32_t a3 = __float_as_uint(xs[(rb + 8) * XST + kk + 4]);
            #pragma unroll
            for (int j = 0; j < 8; j++)
                mma_tf32(d[t][j][0], d[t][j][1], d[t][j][2], d[t][j][3],
                         a0, a1, a2, a3, b0[j], b1[j]);
        }
    }

    // store D as fp16: thread owns fp16x2 word at cols (c, c+1), rows rb, rb+8
    #pragma unroll
    for (int t = 0; t < 2; t++) {
        int r0 = row0 + mrow + t * 16 + l4;
        #pragma unroll
        for (int j = 0; j < 8; j++) {
            int c = ncol + j * 8 + lk * 2;
            uint32_t w0 = hpack(d[t][j][0], d[t][j][1]);
            uint32_t w1 = hpack(d[t][j][2], d[t][j][3]);
            if (r0 < n)     *(uint32_t*)&hout[(size_t)r0 * FOUT + c] = w0;
            if (r0 + 8 < n) *(uint32_t*)&hout[(size_t)(r0 + 8) * FOUT + c] = w1;
        }
    }

    // alpha: 256 threads = 64 rows x 4 heads (tf32-rounded x)
    {
        int r = tid >> 2, h = tid & 3;
        int row = row0 + r;
        if (row < n) {
            float s1 = 0.f, s2 = 0.f;
            #pragma unroll 8
            for (int k = 0; k < FIN; k++) {
                float xv = xs[r * XST + k];
                s1 = fmaf(xv, vs[k * HH + h], s1);
                s2 = fmaf(xv, vd[k * HH + h], s2);
            }
            asrc[row * HH + h] = s1;
            adst[row * HH + h] = s2;
        }
    }
}

// ---------------- per-dst-node softmax + weighted aggregation (1 warp/node)
// No-max softmax (|e| bounded ~0.5 by construction). Lane l owns channels
// [8l, 8l+8); one LDG.128 = 8 fp16 per edge per lane; fp32 accumulation.
__global__ __launch_bounds__(256) void k_aggr(const __half* __restrict__ hf,
                                              const float* __restrict__ asrc,
                                              const float* __restrict__ adst,
                                              const float* __restrict__ bias,
                                              float* __restrict__ out, int n) {
    __shared__ float4 wbuf[8][32];
    __shared__ int    sbuf[8][32];
    int wid = threadIdx.x >> 5;
    int lane = threadIdx.x & 31;
    int node = (blockIdx.x * blockDim.x + threadIdx.x) >> 5;
    if (node >= n) return;

    int base = g_rowptr[node];
    int deg = g_rowptr[node + 1] - base;
    int h = lane >> 3;

    float4 ad = *(const float4*)(adst + (size_t)node * 4);

    float d0 = 0.f, d1 = 0.f, d2 = 0.f, d3 = 0.f;
    unsigned long long acc[4] = {0ull, 0ull, 0ull, 0ull};
    const __half* hlane = hf + lane * 8;

    for (int ib = 0; ib < deg; ib += 32) {
        int rem = min(32, deg - ib);
        {
            int sl = 0;
            float w0 = 0.f, w1 = 0.f, w2 = 0.f, w3 = 0.f;
            if (lane < rem) {
                sl = g_csr[base + ib + lane];
                float4 as = *(const float4*)(asrc + (size_t)sl * 4);
                w0 = __expf(lrelu(as.x + ad.x, 0.2f));
                w1 = __expf(lrelu(as.y + ad.y, 0.2f));
                w2 = __expf(lrelu(as.z + ad.z, 0.2f));
                w3 = __expf(lrelu(as.w + ad.w, 0.2f));
                d0 += w0; d1 += w1; d2 += w2; d3 += w3;
            }
            sbuf[wid][lane] = sl;
            wbuf[wid][lane] = make_float4(w0, w1, w2, w3);
        }
        __syncwarp();
        for (int j = 0; j < rem; j++) {
            int s = sbuf[wid][j];                 // LDS broadcast
            float4 wv = wbuf[wid][j];             // LDS.128 broadcast
            float w = (h == 0) ? wv.x : (h == 1) ? wv.y : (h == 2) ? wv.z : wv.w;
            unsigned long long w2p = pack2(w, w);
            uint4 hv = *(const uint4*)(hlane + (size_t)s * FOUT);  // 8 fp16
            ffma2(acc[0], w2p, h2f2(hv.x));
            ffma2(acc[1], w2p, h2f2(hv.y));
            ffma2(acc[2], w2p, h2f2(hv.z));
            ffma2(acc[3], w2p, h2f2(hv.w));
        }
        __syncwarp();
    }

    #pragma unroll
    for (int o = 16; o; o >>= 1) {
        d0 += __shfl_xor_sync(0xffffffffu, d0, o);
        d1 += __shfl_xor_sync(0xffffffffu, d1, o);
        d2 += __shfl_xor_sync(0xffffffffu, d2, o);
        d3 += __shfl_xor_sync(0xffffffffu, d3, o);
    }
    float i0 = d0 > 0.f ? 0.25f / d0 : 0.f;
    float i1 = d1 > 0.f ? 0.25f / d1 : 0.f;
    float i2 = d2 > 0.f ? 0.25f / d2 : 0.f;
    float i3 = d3 > 0.f ? 0.25f / d3 : 0.f;
    float inv = (h == 0) ? i0 : (h == 1) ? i1 : (h == 2) ? i2 : i3;
    unsigned long long inv2 = pack2(inv, inv);
    #pragma unroll
    for (int j = 0; j < 4; j++) mul2(acc[j], inv2);

    float v[8];
    #pragma unroll
    for (int j = 0; j < 4; j++) { v[2 * j] = lo2(acc[j]); v[2 * j + 1] = hi2(acc[j]); }
    #pragma unroll
    for (int j = 0; j < 8; j++) {
        v[j] += __shfl_xor_sync(0xffffffffu, v[j], 8);
        v[j] += __shfl_xor_sync(0xffffffffu, v[j], 16);
    }

    if (lane < 8) {
        const float4* bp = (const float4*)(bias + lane * 8);
        float4 bA = bp[0], bB = bp[1];
        float4 oA = make_float4(lrelu(v[0] + bA.x, 0.1f), lrelu(v[1] + bA.y, 0.1f),
                                lrelu(v[2] + bA.z, 0.1f), lrelu(v[3] + bA.w, 0.1f));
        float4 oB = make_float4(lrelu(v[4] + bB.x, 0.1f), lrelu(v[5] + bB.y, 0.1f),
                                lrelu(v[6] + bB.z, 0.1f), lrelu(v[7] + bB.w, 0.1f));
        float4* op = (float4*)(out + (size_t)node * CC + lane * 8);
        op[0] = oA;
        op[1] = oB;
    }
}

// ---------------------------------------------------------------------------
extern "C" void kernel_launch(void* const* d_in, const int* in_sizes, int n_in,
                              void* d_out, int out_size) {
    const float* x        = (const float*)d_in[0];
    const int*   ei       = (const int*)d_in[1];
    const float* W1       = (const float*)d_in[2];
    const float* A1       = (const float*)d_in[3];
    const float* att_src1 = (const float*)d_in[4];
    const float* att_dst1 = (const float*)d_in[5];
    const float* b1       = (const float*)d_in[6];
    const float* W2       = (const float*)d_in[7];
    const float* A2       = (const float*)d_in[8];
    const float* att_src2 = (const float*)d_in[9];
    const float* att_dst2 = (const float*)d_in[10];
    const float* b2       = (const float*)d_in[11];
    float* out = (float*)d_out;

    const int n = NN;
    const int eb = (EE + 255) / 256;

    __half* p_h;
    float *p_x2, *p_asrc, *p_adst, *p_vs1, *p_vd1, *p_vs2, *p_vd2;
    cudaGetSymbolAddress((void**)&p_h, g_h);
    cudaGetSymbolAddress((void**)&p_x2, g_x2);
    cudaGetSymbolAddress((void**)&p_asrc, g_asrc);
    cudaGetSymbolAddress((void**)&p_adst, g_adst);
    cudaGetSymbolAddress((void**)&p_vs1, g_vsrc1);
    cudaGetSymbolAddress((void**)&p_vd1, g_vdst1);
    cudaGetSymbolAddress((void**)&p_vs2, g_vsrc2);
    cudaGetSymbolAddress((void**)&p_vd2, g_vdst2);

    // #1 prep (zero counts + detect + both combines)
    k_prep<<<NB2, 256>>>(ei, A1, att_src1, att_dst1, A2, att_src2, att_dst2);
    // #2-#3 CSR start
    k_hist<<<eb, 256>>>(ei);
    k_blocksum<<<NB2, 256>>>();
    // #4 gemm1 (profiler captures launch #4; independent of CSR)
    k_gemm<128><<<(n + 63) / 64, 256>>>(x, W1, p_h, p_vs1, p_vd1, p_asrc, p_adst, n);
    // #5-#7 CSR finish
    k_scanb<<<1, 256>>>(NB2);
    k_writeoff<<<NB2, 256>>>();
    k_scatter<<<eb, 256>>>(ei);
    // #8 layer-1 aggregation
    k_aggr<<<(n * 32 + 255) / 256, 256>>>(p_h, p_asrc, p_adst, b1, p_x2, n);
    // #9-#10 layer 2
    k_gemm<64><<<(n + 63) / 64, 256>>>(p_x2, W2, p_h, p_vs2, p_vd2, p_asrc, p_adst, n);
    k_aggr<<<(n * 32 + 255) / 256, 256>>>(p_h, p_asrc, p_adst, b2, out, n);
}

// round 14
// speedup vs baseline: 1.5724x; 1.0659x over previous
#include <cuda_runtime.h>
#include <cuda_fp16.h>
#include <cuda_bf16.h>
#include <cstdint>

// Problem constants
#define NN   50000
#define EE   800000
#define HH   4
#define CC   64
#define DD   4
#define FOUT 256   // H*C
#define NB2  ((NN + 255) / 256)   // 196 blocks of 256

// ---------------- scratch (device globals; no allocation allowed) ----------
__device__ __align__(16) __half g_h[(size_t)NN * FOUT];   // h messages, fp16
__device__ __align__(16) float g_x2[(size_t)NN * CC];     // layer-1 output
__device__ __align__(16) float g_asrc[NN * HH];
__device__ __align__(16) float g_adst[NN * HH];
__device__ __align__(16) float g_vsrc1[128 * HH];
__device__ __align__(16) float g_vdst1[128 * HH];
__device__ __align__(16) float g_vsrc2[64 * HH];
__device__ __align__(16) float g_vdst2[64 * HH];
__device__ int g_count[NN];
__device__ int g_off[NN];
__device__ int g_rowptr[NN + 1];
__device__ int g_csr[EE];
__device__ int g_is64;
__device__ int g_bsum[256];
__device__ int g_bpre[256];

__device__ __forceinline__ float lrelu(float v, float s) { return v >= 0.f ? v : s * v; }

// 32-bit edge-index load: element i is the low word at 2*i (int64 LE) or
// word i (int32). Node ids < 50000 always fit in the low 32 bits.
__device__ __forceinline__ int edge_lo(const int* ei_words, size_t i, int is64) {
    return ei_words[is64 ? 2 * i : i];
}

// packed f32x2 helpers (sm_103a)
__device__ __forceinline__ unsigned long long pack2(float lo, float hi) {
    unsigned long long r;
    asm("mov.b64 %0, {%1, %2};" : "=l"(r) : "f"(lo), "f"(hi));
    return r;
}
__device__ __forceinline__ void ffma2(unsigned long long& d, unsigned long long a,
                                      unsigned long long b) {
    asm("fma.rn.f32x2 %0, %1, %2, %0;" : "+l"(d) : "l"(a), "l"(b));
}
__device__ __forceinline__ void mul2(unsigned long long& d, unsigned long long a) {
    asm("mul.rn.f32x2 %0, %0, %1;" : "+l"(d) : "l"(a));
}
__device__ __forceinline__ float lo2(unsigned long long v) {
    float a, b; asm("mov.b64 {%0, %1}, %2;" : "=f"(a), "=f"(b) : "l"(v)); return a;
}
__device__ __forceinline__ float hi2(unsigned long long v) {
    float a, b; asm("mov.b64 {%0, %1}, %2;" : "=f"(a), "=f"(b) : "l"(v)); return b;
}
// half2 word -> packed f32x2
__device__ __forceinline__ unsigned long long h2f2(uint32_t u) {
    __half2 h = *reinterpret_cast<__half2*>(&u);
    float2 f = __half22float2(h);
    return pack2(f.x, f.y);
}
// pack (lo=a, hi=b) into fp16x2 word
__device__ __forceinline__ uint32_t hpack(float a, float b) {
    uint32_t r;
    asm("cvt.rn.f16x2.f32 %0, %1, %2;" : "=r"(r) : "f"(b), "f"(a));
    return r;
}

// fp16 tensor-core mma: D(16x8,f32) += A(16x16,f16,row) * B(16x8,f16,col)
__device__ __forceinline__ void mma_f16(float& d0, float& d1, float& d2, float& d3,
                                        uint32_t a0, uint32_t a1, uint32_t a2, uint32_t a3,
                                        uint32_t b0, uint32_t b1) {
    asm("mma.sync.aligned.m16n8k16.row.col.f32.f16.f16.f32 "
        "{%0,%1,%2,%3}, {%4,%5,%6,%7}, {%8,%9}, {%0,%1,%2,%3};"
        : "+f"(d0), "+f"(d1), "+f"(d2), "+f"(d3)
        : "r"(a0), "r"(a1), "r"(a2), "r"(a3), "r"(b0), "r"(b1));
}

// ---------------- fused prep: zero counts + dtype detect + both combines ---
__global__ __launch_bounds__(256) void k_prep(const int* ei_words,
                                              const float* __restrict__ A1,
                                              const float* __restrict__ as1,
                                              const float* __restrict__ ad1,
                                              const float* __restrict__ A2,
                                              const float* __restrict__ as2,
                                              const float* __restrict__ ad2) {
    int i = blockIdx.x * 256 + threadIdx.x;
    if (i < NN) g_count[i] = 0;
    if (i == 0) {
        int nz = 0;
        for (int j = 0; j < 64; j++)
            if (ei_words[2 * j + 1] != 0) nz++;
        g_is64 = (nz == 0) ? 1 : 0;
    }
    if (i < 128 * HH) {
        int f = i >> 2, h = i & 3;
        float s1 = 0.f, s2 = 0.f;
        #pragma unroll
        for (int d = 0; d < DD; d++) {
            float a = A1[f * (HH * DD) + h * DD + d];
            s1 += a * as1[h * DD + d];
            s2 += a * ad1[h * DD + d];
        }
        g_vsrc1[f * HH + h] = s1;
        g_vdst1[f * HH + h] = s2;
    }
    if (i < 64 * HH) {
        int f = i >> 2, h = i & 3;
        float s1 = 0.f, s2 = 0.f;
        #pragma unroll
        for (int d = 0; d < DD; d++) {
            float a = A2[f * (HH * DD) + h * DD + d];
            s1 += a * as2[h * DD + d];
            s2 += a * ad2[h * DD + d];
        }
        g_vsrc2[f * HH + h] = s1;
        g_vdst2[f * HH + h] = s2;
    }
}

__global__ void k_hist(const int* ei_words) {
    int e = blockIdx.x * blockDim.x + threadIdx.x;
    if (e >= EE) return;
    int dst = edge_lo(ei_words, (size_t)EE + e, g_is64);
    atomicAdd(&g_count[dst], 1);
}

// ---- parallel scan: blocksum -> scan of partials -> per-block writeout ----
__global__ __launch_bounds__(256) void k_blocksum() {
    __shared__ int sh[8];
    int i = blockIdx.x * 256 + threadIdx.x;
    int v = (i < NN) ? g_count[i] : 0;
    #pragma unroll
    for (int o = 16; o; o >>= 1) v += __shfl_xor_sync(0xffffffffu, v, o);
    if ((threadIdx.x & 31) == 0) sh[threadIdx.x >> 5] = v;
    __syncthreads();
    if (threadIdx.x == 0) {
        int s = 0;
        #pragma unroll
        for (int j = 0; j < 8; j++) s += sh[j];
        g_bsum[blockIdx.x] = s;
    }
}

__global__ __launch_bounds__(256) void k_scanb(int nb) {
    __shared__ int sh[256];
    int t = threadIdx.x;
    int v = (t < nb) ? g_bsum[t] : 0;
    sh[t] = v;
    __syncthreads();
    for (int o = 1; o < 256; o <<= 1) {
        int u = (t >= o) ? sh[t - o] : 0;
        __syncthreads();
        sh[t] += u;
        __syncthreads();
    }
    if (t < nb) g_bpre[t] = sh[t] - v;  // exclusive
}

__global__ __launch_bounds__(256) void k_writeoff() {
    __shared__ int wpre[8];
    int t = threadIdx.x;
    int lane = t & 31, w = t >> 5;
    int i = blockIdx.x * 256 + t;
    int c = (i < NN) ? g_count[i] : 0;
    int v = c;
    #pragma unroll
    for (int o = 1; o < 32; o <<= 1) {
        int u = __shfl_up_sync(0xffffffffu, v, o);
        if (lane >= o) v += u;
    }
    if (lane == 31) wpre[w] = v;
    __syncthreads();
    if (t == 0) {
        int run = 0;
        #pragma unroll
        for (int j = 0; j < 8; j++) { int tmp = wpre[j]; wpre[j] = run; run += tmp; }
    }
    __syncthreads();
    int excl = v - c + wpre[w] + g_bpre[blockIdx.x];
    if (i < NN) {
        g_rowptr[i] = excl;
        g_off[i] = excl;
        if (i == NN - 1) g_rowptr[NN] = excl + c;
    }
}

__global__ void k_scatter(const int* ei_words) {
    int e = blockIdx.x * blockDim.x + threadIdx.x;
    if (e >= EE) return;
    int is64 = g_is64;
    int src = edge_lo(ei_words, (size_t)e, is64);
    int dst = edge_lo(ei_words, (size_t)EE + e, is64);
    int pos = atomicAdd(&g_off[dst], 1);
    g_csr[pos] = src;
}

// ---------------- fp16 tensor-core GEMM (m16n8k16) + W reg prefetch --------
// 256 thr = 8 warps; block tile 64 rows x 256 cols; warp tile 32 x 64.
// K consumed 16/chunk -> FIN/16 barrier phases (half of tf32 version).
// xs: half2 words, stride XSTW = FIN/2+4 (== 4 mod 32) -> A-frag LDS
//   conflict-free (bank = 4*l4 + lk covers 0..31).
// wsT: W chunk TRANSPOSED [col][kpair], stride KST2 = 9 words (9 coprime 32
//   -> STS conflict-free; B-frag LDS worst-case 2-way on 3 banks).
template <int FIN>
__global__ __launch_bounds__(256, 2) void k_gemm(const float* __restrict__ x,
                                                 const float* __restrict__ W,
                                                 __half* __restrict__ hout,
                                                 const float* __restrict__ vs,
                                                 const float* __restrict__ vd,
                                                 float* __restrict__ asrc,
                                                 float* __restrict__ adst, int n) {
    constexpr int KW = FIN / 2;        // half2 words per row of x
    constexpr int XSTW = KW + 4;       // == 4 mod 32
    constexpr int KST2 = 9;            // half2 words per wsT column
    __shared__ uint32_t xs[64 * XSTW];
    __shared__ uint32_t wsT[256 * KST2];
    int tid = threadIdx.x;
    int lane = tid & 31;
    int w = tid >> 5;
    int row0 = blockIdx.x * 64;
    int mrow = (w >> 2) * 32;
    int ncol = (w & 3) * 64;
    int l4 = lane >> 2;       // 0..7
    int lk = lane & 3;        // 0..3

    // load x tile -> fp16 pairs
    for (int idx = tid; idx < 64 * KW; idx += 256) {
        int r = idx / KW, kp = idx - r * KW;
        int row = row0 + r;
        float v0 = 0.f, v1 = 0.f;
        if (row < n) {
            const float2 xv = *(const float2*)&x[(size_t)row * FIN + 2 * kp];
            v0 = xv.x; v1 = xv.y;
        }
        xs[r * XSTW + kp] = hpack(v0, v1);
    }

    // prefetch chunk 0 of W: rows 0..15, col tid
    float wreg[16];
    #pragma unroll
    for (int i = 0; i < 16; i++) wreg[i] = W[(size_t)i * FOUT + tid];

    float d[2][8][4];
    #pragma unroll
    for (int t = 0; t < 2; t++)
        #pragma unroll
        for (int j = 0; j < 8; j++)
            #pragma unroll
            for (int q = 0; q < 4; q++) d[t][j][q] = 0.f;

    for (int kc = 0; kc < FIN; kc += 16) {
        __syncthreads();   // wsT free (first iter: xs writes ordered)
        #pragma unroll
        for (int i = 0; i < 8; i++)
            wsT[tid * KST2 + i] = hpack(wreg[2 * i], wreg[2 * i + 1]);
        __syncthreads();

        // prefetch next chunk while computing this one
        if (kc + 16 < FIN) {
            #pragma unroll
            for (int i = 0; i < 16; i++)
                wreg[i] = W[(size_t)(kc + 16 + i) * FOUT + tid];
        }

        // B fragments (shared by both m-tiles)
        uint32_t b0[8], b1[8];
        #pragma unroll
        for (int j = 0; j < 8; j++) {
            int col = ncol + j * 8 + l4;
            b0[j] = wsT[col * KST2 + lk];
            b1[j] = wsT[col * KST2 + lk + 4];
        }
        int kw = (kc >> 1) + lk;
        #pragma unroll
        for (int t = 0; t < 2; t++) {
            int rb = mrow + t * 16 + l4;
            uint32_t a0 = xs[rb * XSTW + kw];
            uint32_t a1 = xs[(rb + 8) * XSTW + kw];
            uint32_t a2 = xs[rb * XSTW + kw + 4];
            uint32_t a3 = xs[(rb + 8) * XSTW + kw + 4];
            #pragma unroll
            for (int j = 0; j < 8; j++)
                mma_f16(d[t][j][0], d[t][j][1], d[t][j][2], d[t][j][3],
                        a0, a1, a2, a3, b0[j], b1[j]);
        }
    }

    // store D as fp16: thread owns fp16x2 word at cols (c, c+1), rows rb, rb+8
    #pragma unroll
    for (int t = 0; t < 2; t++) {
        int r0 = row0 + mrow + t * 16 + l4;
        #pragma unroll
        for (int j = 0; j < 8; j++) {
            int c = ncol + j * 8 + lk * 2;
            uint32_t w0 = hpack(d[t][j][0], d[t][j][1]);
            uint32_t w1 = hpack(d[t][j][2], d[t][j][3]);
            if (r0 < n)     *(uint32_t*)&hout[(size_t)r0 * FOUT + c] = w0;
            if (r0 + 8 < n) *(uint32_t*)&hout[(size_t)(r0 + 8) * FOUT + c] = w1;
        }
    }

    // alpha: 256 threads = 64 rows x 4 heads (fp16-rounded x, fp32 accum)
    {
        int r = tid >> 2, h = tid & 3;
        int row = row0 + r;
        if (row < n) {
            float s1 = 0.f, s2 = 0.f;
            #pragma unroll 4
            for (int kp = 0; kp < KW; kp++) {
                uint32_t u = xs[r * XSTW + kp];
                __half2 hh = *reinterpret_cast<__half2*>(&u);
                float2 f = __half22float2(hh);
                s1 = fmaf(f.x, vs[(2 * kp) * HH + h], s1);
                s1 = fmaf(f.y, vs[(2 * kp + 1) * HH + h], s1);
                s2 = fmaf(f.x, vd[(2 * kp) * HH + h], s2);
                s2 = fmaf(f.y, vd[(2 * kp + 1) * HH + h], s2);
            }
            asrc[row * HH + h] = s1;
            adst[row * HH + h] = s2;
        }
    }
}

// ---------------- per-dst-node softmax + weighted aggregation (1 warp/node)
// No-max softmax (|e| bounded ~0.5 by construction). Lane l owns channels
// [8l, 8l+8); one LDG.128 = 8 fp16 per edge per lane; fp32 accumulation.
__global__ __launch_bounds__(256) void k_aggr(const __half* __restrict__ hf,
                                              const float* __restrict__ asrc,
                                              const float* __restrict__ adst,
                                              const float* __restrict__ bias,
                                              float* __restrict__ out, int n) {
    __shared__ float4 wbuf[8][32];
    __shared__ int    sbuf[8][32];
    int wid = threadIdx.x >> 5;
    int lane = threadIdx.x & 31;
    int node = (blockIdx.x * blockDim.x + threadIdx.x) >> 5;
    if (node >= n) return;

    int base = g_rowptr[node];
    int deg = g_rowptr[node + 1] - base;
    int h = lane >> 3;

    float4 ad = *(const float4*)(adst + (size_t)node * 4);

    float d0 = 0.f, d1 = 0.f, d2 = 0.f, d3 = 0.f;
    unsigned long long acc[4] = {0ull, 0ull, 0ull, 0ull};
    const __half* hlane = hf + lane * 8;

    for (int ib = 0; ib < deg; ib += 32) {
        int rem = min(32, deg - ib);
        {
            int sl = 0;
            float w0 = 0.f, w1 = 0.f, w2 = 0.f, w3 = 0.f;
            if (lane < rem) {
                sl = g_csr[base + ib + lane];
                float4 as = *(const float4*)(asrc + (size_t)sl * 4);
                w0 = __expf(lrelu(as.x + ad.x, 0.2f));
                w1 = __expf(lrelu(as.y + ad.y, 0.2f));
                w2 = __expf(lrelu(as.z + ad.z, 0.2f));
                w3 = __expf(lrelu(as.w + ad.w, 0.2f));
                d0 += w0; d1 += w1; d2 += w2; d3 += w3;
            }
            sbuf[wid][lane] = sl;
            wbuf[wid][lane] = make_float4(w0, w1, w2, w3);
        }
        __syncwarp();
        for (int j = 0; j < rem; j++) {
            int s = sbuf[wid][j];                 // LDS broadcast
            float4 wv = wbuf[wid][j];             // LDS.128 broadcast
            float w = (h == 0) ? wv.x : (h == 1) ? wv.y : (h == 2) ? wv.z : wv.w;
            unsigned long long w2p = pack2(w, w);
            uint4 hv = *(const uint4*)(hlane + (size_t)s * FOUT);  // 8 fp16
            ffma2(acc[0], w2p, h2f2(hv.x));
            ffma2(acc[1], w2p, h2f2(hv.y));
            ffma2(acc[2], w2p, h2f2(hv.z));
            ffma2(acc[3], w2p, h2f2(hv.w));
        }
        __syncwarp();
    }

    #pragma unroll
    for (int o = 16; o; o >>= 1) {
        d0 += __shfl_xor_sync(0xffffffffu, d0, o);
        d1 += __shfl_xor_sync(0xffffffffu, d1, o);
        d2 += __shfl_xor_sync(0xffffffffu, d2, o);
        d3 += __shfl_xor_sync(0xffffffffu, d3, o);
    }
    float i0 = d0 > 0.f ? 0.25f / d0 : 0.f;
    float i1 = d1 > 0.f ? 0.25f / d1 : 0.f;
    float i2 = d2 > 0.f ? 0.25f / d2 : 0.f;
    float i3 = d3 > 0.f ? 0.25f / d3 : 0.f;
    float inv = (h == 0) ? i0 : (h == 1) ? i1 : (h == 2) ? i2 : i3;
    unsigned long long inv2 = pack2(inv, inv);
    #pragma unroll
    for (int j = 0; j < 4; j++) mul2(acc[j], inv2);

    float v[8];
    #pragma unroll
    for (int j = 0; j < 4; j++) { v[2 * j] = lo2(acc[j]); v[2 * j + 1] = hi2(acc[j]); }
    #pragma unroll
    for (int j = 0; j < 8; j++) {
        v[j] += __shfl_xor_sync(0xffffffffu, v[j], 8);
        v[j] += __shfl_xor_sync(0xffffffffu, v[j], 16);
    }

    if (lane < 8) {
        const float4* bp = (const float4*)(bias + lane * 8);
        float4 bA = bp[0], bB = bp[1];
        float4 oA = make_float4(lrelu(v[0] + bA.x, 0.1f), lrelu(v[1] + bA.y, 0.1f),
                                lrelu(v[2] + bA.z, 0.1f), lrelu(v[3] + bA.w, 0.1f));
        float4 oB = make_float4(lrelu(v[4] + bB.x, 0.1f), lrelu(v[5] + bB.y, 0.1f),
                                lrelu(v[6] + bB.z, 0.1f), lrelu(v[7] + bB.w, 0.1f));
        float4* op = (float4*)(out + (size_t)node * CC + lane * 8);
        op[0] = oA;
        op[1] = oB;
    }
}

// ---------------------------------------------------------------------------
extern "C" void kernel_launch(void* const* d_in, const int* in_sizes, int n_in,
                              void* d_out, int out_size) {
    const float* x        = (const float*)d_in[0];
    const int*   ei       = (const int*)d_in[1];
    const float* W1       = (const float*)d_in[2];
    const float* A1       = (const float*)d_in[3];
    const float* att_src1 = (const float*)d_in[4];
    const float* att_dst1 = (const float*)d_in[5];
    const float* b1       = (const float*)d_in[6];
    const float* W2       = (const float*)d_in[7];
    const float* A2       = (const float*)d_in[8];
    const float* att_src2 = (const float*)d_in[9];
    const float* att_dst2 = (const float*)d_in[10];
    const float* b2       = (const float*)d_in[11];
    float* out = (float*)d_out;

    const int n = NN;
    const int eb = (EE + 255) / 256;

    __half* p_h;
    float *p_x2, *p_asrc, *p_adst, *p_vs1, *p_vd1, *p_vs2, *p_vd2;
    cudaGetSymbolAddress((void**)&p_h, g_h);
    cudaGetSymbolAddress((void**)&p_x2, g_x2);
    cudaGetSymbolAddress((void**)&p_asrc, g_asrc);
    cudaGetSymbolAddress((void**)&p_adst, g_adst);
    cudaGetSymbolAddress((void**)&p_vs1, g_vsrc1);
    cudaGetSymbolAddress((void**)&p_vd1, g_vdst1);
    cudaGetSymbolAddress((void**)&p_vs2, g_vsrc2);
    cudaGetSymbolAddress((void**)&p_vd2, g_vdst2);

    // #1 prep (zero counts + detect + both combines)
    k_prep<<<NB2, 256>>>(ei, A1, att_src1, att_dst1, A2, att_src2, att_dst2);
    // #2-#3 CSR start
    k_hist<<<eb, 256>>>(ei);
    k_blocksum<<<NB2, 256>>>();
    // #4 gemm1 (profiler captures launch #4; independent of CSR)
    k_gemm<128><<<(n + 63) / 64, 256>>>(x, W1, p_h, p_vs1, p_vd1, p_asrc, p_adst, n);
    // #5-#7 CSR finish
    k_scanb<<<1, 256>>>(NB2);
    k_writeoff<<<NB2, 256>>>();
    k_scatter<<<eb, 256>>>(ei);
    // #8 layer-1 aggregation
    k_aggr<<<(n * 32 + 255) / 256, 256>>>(p_h, p_asrc, p_adst, b1, p_x2, n);
    // #9-#10 layer 2
    k_gemm<64><<<(n + 63) / 64, 256>>>(p_x2, W2, p_h, p_vs2, p_vd2, p_asrc, p_adst, n);
    k_aggr<<<(n * 32 + 255) / 256, 256>>>(p_h, p_asrc, p_adst, b2, out, n);
}

// round 15
// speedup vs baseline: 1.7509x; 1.1135x over previous
#include <cuda_runtime.h>
#include <cuda_fp16.h>
#include <cuda_bf16.h>
#include <cstdint>

// Problem constants
#define NN   50000
#define EE   800000
#define HH   4
#define CC   64
#define DD   4
#define FOUT 256   // H*C
#define NB2  ((NN + 255) / 256)   // 196 blocks of 256

// ---------------- scratch (device globals; no allocation allowed) ----------
__device__ __align__(16) __half g_h[(size_t)NN * FOUT];   // h messages, fp16
__device__ __align__(16) float g_x2[(size_t)NN * CC];     // layer-1 output
__device__ __align__(16) float g_asrc[NN * HH];
__device__ __align__(16) float g_adst[NN * HH];
__device__ __align__(16) float g_vsrc1[128 * HH];
__device__ __align__(16) float g_vdst1[128 * HH];
__device__ __align__(16) float g_vsrc2[64 * HH];
__device__ __align__(16) float g_vdst2[64 * HH];
__device__ int g_count[NN];      // zero at start of every run (static init +
                                 // re-zeroed by k_writeoff each run)
__device__ int g_off[NN];
__device__ int g_rowptr[NN + 1];
__device__ int g_csr[EE];
__device__ int g_is64;
__device__ int g_bsum[256];
__device__ int g_bpre[256];
__device__ int g_done;           // blocksum completion counter (self-resetting)

__device__ __forceinline__ float lrelu(float v, float s) { return v >= 0.f ? v : s * v; }

// 32-bit edge-index load: element i is the low word at 2*i (int64 LE) or
// word i (int32). Node ids < 50000 always fit in the low 32 bits.
__device__ __forceinline__ int edge_lo(const int* ei_words, size_t i, int is64) {
    return ei_words[is64 ? 2 * i : i];
}

// packed f32x2 helpers (sm_103a)
__device__ __forceinline__ unsigned long long pack2(float lo, float hi) {
    unsigned long long r;
    asm("mov.b64 %0, {%1, %2};" : "=l"(r) : "f"(lo), "f"(hi));
    return r;
}
__device__ __forceinline__ void ffma2(unsigned long long& d, unsigned long long a,
                                      unsigned long long b) {
    asm("fma.rn.f32x2 %0, %1, %2, %0;" : "+l"(d) : "l"(a), "l"(b));
}
__device__ __forceinline__ void mul2(unsigned long long& d, unsigned long long a) {
    asm("mul.rn.f32x2 %0, %0, %1;" : "+l"(d) : "l"(a));
}
__device__ __forceinline__ float lo2(unsigned long long v) {
    float a, b; asm("mov.b64 {%0, %1}, %2;" : "=f"(a), "=f"(b) : "l"(v)); return a;
}
__device__ __forceinline__ float hi2(unsigned long long v) {
    float a, b; asm("mov.b64 {%0, %1}, %2;" : "=f"(a), "=f"(b) : "l"(v)); return b;
}
// half2 word -> packed f32x2
__device__ __forceinline__ unsigned long long h2f2(uint32_t u) {
    __half2 h = *reinterpret_cast<__half2*>(&u);
    float2 f = __half22float2(h);
    return pack2(f.x, f.y);
}
// pack (lo=a, hi=b) into fp16x2 word
__device__ __forceinline__ uint32_t hpack(float a, float b) {
    uint32_t r;
    asm("cvt.rn.f16x2.f32 %0, %1, %2;" : "=r"(r) : "f"(b), "f"(a));
    return r;
}

// fp16 tensor-core mma: D(16x8,f32) += A(16x16,f16,row) * B(16x8,f16,col)
__device__ __forceinline__ void mma_f16(float& d0, float& d1, float& d2, float& d3,
                                        uint32_t a0, uint32_t a1, uint32_t a2, uint32_t a3,
                                        uint32_t b0, uint32_t b1) {
    asm("mma.sync.aligned.m16n8k16.row.col.f32.f16.f16.f32 "
        "{%0,%1,%2,%3}, {%4,%5,%6,%7}, {%8,%9}, {%0,%1,%2,%3};"
        : "+f"(d0), "+f"(d1), "+f"(d2), "+f"(d3)
        : "r"(a0), "r"(a1), "r"(a2), "r"(a3), "r"(b0), "r"(b1));
}

// ---------------- prep: dtype detect + both A*att combines (2 blocks) ------
__global__ __launch_bounds__(256) void k_prep(const int* ei_words,
                                              const float* __restrict__ A1,
                                              const float* __restrict__ as1,
                                              const float* __restrict__ ad1,
                                              const float* __restrict__ A2,
                                              const float* __restrict__ as2,
                                              const float* __restrict__ ad2) {
    int i = blockIdx.x * 256 + threadIdx.x;
    if (i == 0) {
        int nz = 0;
        for (int j = 0; j < 64; j++)
            if (ei_words[2 * j + 1] != 0) nz++;
        g_is64 = (nz == 0) ? 1 : 0;
    }
    if (i < 128 * HH) {
        int f = i >> 2, h = i & 3;
        float s1 = 0.f, s2 = 0.f;
        #pragma unroll
        for (int d = 0; d < DD; d++) {
            float a = A1[f * (HH * DD) + h * DD + d];
            s1 += a * as1[h * DD + d];
            s2 += a * ad1[h * DD + d];
        }
        g_vsrc1[f * HH + h] = s1;
        g_vdst1[f * HH + h] = s2;
    }
    if (i < 64 * HH) {
        int f = i >> 2, h = i & 3;
        float s1 = 0.f, s2 = 0.f;
        #pragma unroll
        for (int d = 0; d < DD; d++) {
            float a = A2[f * (HH * DD) + h * DD + d];
            s1 += a * as2[h * DD + d];
            s2 += a * ad2[h * DD + d];
        }
        g_vsrc2[f * HH + h] = s1;
        g_vdst2[f * HH + h] = s2;
    }
}

__global__ void k_hist(const int* ei_words) {
    int e = blockIdx.x * blockDim.x + threadIdx.x;
    if (e >= EE) return;
    int dst = edge_lo(ei_words, (size_t)EE + e, g_is64);
    atomicAdd(&g_count[dst], 1);
}

// ---- fused blocksum + scan-of-partials (last-block-done pattern) ----------
__global__ __launch_bounds__(256) void k_blocksum_scan() {
    __shared__ int sh[256];
    __shared__ bool last;
    int tid = threadIdx.x;
    int i = blockIdx.x * 256 + tid;
    int v = (i < NN) ? g_count[i] : 0;
    #pragma unroll
    for (int o = 16; o; o >>= 1) v += __shfl_xor_sync(0xffffffffu, v, o);
    if ((tid & 31) == 0) sh[tid >> 5] = v;
    __syncthreads();
    if (tid == 0) {
        int s = 0;
        #pragma unroll
        for (int j = 0; j < 8; j++) s += sh[j];
        g_bsum[blockIdx.x] = s;
        __threadfence();
        int prev = atomicAdd(&g_done, 1);
        last = (prev == (int)gridDim.x - 1);
    }
    __syncthreads();
    if (last) {
        __threadfence();   // acquire all blocks' g_bsum writes
        int nb = gridDim.x;
        int b = (tid < nb) ? g_bsum[tid] : 0;
        sh[tid] = b;
        __syncthreads();
        for (int o = 1; o < 256; o <<= 1) {
            int u = (tid >= o) ? sh[tid - o] : 0;
            __syncthreads();
            sh[tid] += u;
            __syncthreads();
        }
        if (tid < nb) g_bpre[tid] = sh[tid] - b;  // exclusive
        if (tid == 0) g_done = 0;                 // reset for next run
    }
}

__global__ __launch_bounds__(256) void k_writeoff() {
    __shared__ int wpre[8];
    int t = threadIdx.x;
    int lane = t & 31, w = t >> 5;
    int i = blockIdx.x * 256 + t;
    int c = (i < NN) ? g_count[i] : 0;
    int v = c;
    #pragma unroll
    for (int o = 1; o < 32; o <<= 1) {
        int u = __shfl_up_sync(0xffffffffu, v, o);
        if (lane >= o) v += u;
    }
    if (lane == 31) wpre[w] = v;
    __syncthreads();
    if (t == 0) {
        int run = 0;
        #pragma unroll
        for (int j = 0; j < 8; j++) { int tmp = wpre[j]; wpre[j] = run; run += tmp; }
    }
    __syncthreads();
    int excl = v - c + wpre[w] + g_bpre[blockIdx.x];
    if (i < NN) {
        g_rowptr[i] = excl;
        g_off[i] = excl;
        g_count[i] = 0;    // counts are dead: re-zero for the next run
        if (i == NN - 1) g_rowptr[NN] = excl + c;
    }
}

__global__ void k_scatter(const int* ei_words) {
    int e = blockIdx.x * blockDim.x + threadIdx.x;
    if (e >= EE) return;
    int is64 = g_is64;
    int src = edge_lo(ei_words, (size_t)e, is64);
    int dst = edge_lo(ei_words, (size_t)EE + e, is64);
    int pos = atomicAdd(&g_off[dst], 1);
    g_csr[pos] = src;
}

// ---------------- fp16 tensor-core GEMM (m16n8k16) + W reg prefetch --------
// 256 thr = 8 warps; block tile 64 rows x 256 cols; warp tile 32 x 64.
// xs: half2 words, stride XSTW = FIN/2+4 (== 4 mod 32): A-frag LDS clean.
// wsT: W chunk transposed [col][kpair], stride 9 (coprime 32): STS clean.
// vs/vd staged in smem: alpha epilogue reads broadcast LDS, not global LDG.
template <int FIN>
__global__ __launch_bounds__(256, 2) void k_gemm(const float* __restrict__ x,
                                                 const float* __restrict__ W,
                                                 __half* __restrict__ hout,
                                                 const float* __restrict__ vs,
                                                 const float* __restrict__ vd,
                                                 float* __restrict__ asrc,
                                                 float* __restrict__ adst, int n) {
    constexpr int KW = FIN / 2;        // half2 words per row of x
    constexpr int XSTW = KW + 4;       // == 4 mod 32
    constexpr int KST2 = 9;            // half2 words per wsT column
    __shared__ uint32_t xs[64 * XSTW];
    __shared__ uint32_t wsT[256 * KST2];
    __shared__ float svs[FIN * HH];
    __shared__ float svd[FIN * HH];
    int tid = threadIdx.x;
    int lane = tid & 31;
    int w = tid >> 5;
    int row0 = blockIdx.x * 64;
    int mrow = (w >> 2) * 32;
    int ncol = (w & 3) * 64;
    int l4 = lane >> 2;       // 0..7
    int lk = lane & 3;        // 0..3

    // load x tile -> fp16 pairs
    for (int idx = tid; idx < 64 * KW; idx += 256) {
        int r = idx / KW, kp = idx - r * KW;
        int row = row0 + r;
        float v0 = 0.f, v1 = 0.f;
        if (row < n) {
            const float2 xv = *(const float2*)&x[(size_t)row * FIN + 2 * kp];
            v0 = xv.x; v1 = xv.y;
        }
        xs[r * XSTW + kp] = hpack(v0, v1);
    }
    // stage vs/vd in smem
    for (int idx = tid; idx < FIN * HH; idx += 256) {
        svs[idx] = vs[idx];
        svd[idx] = vd[idx];
    }

    // prefetch chunk 0 of W: rows 0..15, col tid
    float wreg[16];
    #pragma unroll
    for (int i = 0; i < 16; i++) wreg[i] = W[(size_t)i * FOUT + tid];

    float d[2][8][4];
    #pragma unroll
    for (int t = 0; t < 2; t++)
        #pragma unroll
        for (int j = 0; j < 8; j++)
            #pragma unroll
            for (int q = 0; q < 4; q++) d[t][j][q] = 0.f;

    for (int kc = 0; kc < FIN; kc += 16) {
        __syncthreads();   // wsT free (first iter: xs/svs writes ordered)
        #pragma unroll
        for (int i = 0; i < 8; i++)
            wsT[tid * KST2 + i] = hpack(wreg[2 * i], wreg[2 * i + 1]);
        __syncthreads();

        // prefetch next chunk while computing this one
        if (kc + 16 < FIN) {
            #pragma unroll
            for (int i = 0; i < 16; i++)
                wreg[i] = W[(size_t)(kc + 16 + i) * FOUT + tid];
        }

        // B fragments (shared by both m-tiles)
        uint32_t b0[8], b1[8];
        #pragma unroll
        for (int j = 0; j < 8; j++) {
            int col = ncol + j * 8 + l4;
            b0[j] = wsT[col * KST2 + lk];
            b1[j] = wsT[col * KST2 + lk + 4];
        }
        int kw = (kc >> 1) + lk;
        #pragma unroll
        for (int t = 0; t < 2; t++) {
            int rb = mrow + t * 16 + l4;
            uint32_t a0 = xs[rb * XSTW + kw];
            uint32_t a1 = xs[(rb + 8) * XSTW + kw];
            uint32_t a2 = xs[rb * XSTW + kw + 4];
            uint32_t a3 = xs[(rb + 8) * XSTW + kw + 4];
            #pragma unroll
            for (int j = 0; j < 8; j++)
                mma_f16(d[t][j][0], d[t][j][1], d[t][j][2], d[t][j][3],
                        a0, a1, a2, a3, b0[j], b1[j]);
        }
    }

    // store D as fp16: thread owns fp16x2 word at cols (c, c+1), rows rb, rb+8
    #pragma unroll
    for (int t = 0; t < 2; t++) {
        int r0 = row0 + mrow + t * 16 + l4;
        #pragma unroll
        for (int j = 0; j < 8; j++) {
            int c = ncol + j * 8 + lk * 2;
            uint32_t w0 = hpack(d[t][j][0], d[t][j][1]);
            uint32_t w1 = hpack(d[t][j][2], d[t][j][3]);
            if (r0 < n)     *(uint32_t*)&hout[(size_t)r0 * FOUT + c] = w0;
            if (r0 + 8 < n) *(uint32_t*)&hout[(size_t)(r0 + 8) * FOUT + c] = w1;
        }
    }

    // alpha: 256 threads = 64 rows x 4 heads (fp16-rounded x, fp32 accum,
    // vs/vd broadcast from smem)
    {
        int r = tid >> 2, h = tid & 3;
        int row = row0 + r;
        if (row < n) {
            float s1 = 0.f, s2 = 0.f;
            #pragma unroll 4
            for (int kp = 0; kp < KW; kp++) {
                uint32_t u = xs[r * XSTW + kp];
                __half2 hh = *reinterpret_cast<__half2*>(&u);
                float2 f = __half22float2(hh);
                s1 = fmaf(f.x, svs[(2 * kp) * HH + h], s1);
                s1 = fmaf(f.y, svs[(2 * kp + 1) * HH + h], s1);
                s2 = fmaf(f.x, svd[(2 * kp) * HH + h], s2);
                s2 = fmaf(f.y, svd[(2 * kp + 1) * HH + h], s2);
            }
            asrc[row * HH + h] = s1;
            adst[row * HH + h] = s2;
        }
    }
}

// ---------------- per-dst-node softmax + weighted aggregation (1 warp/node)
// No-max softmax (|e| bounded ~0.5 by construction). Lane l owns channels
// [8l, 8l+8); one LDG.128 = 8 fp16 per edge per lane; fp32 accumulation.
__global__ __launch_bounds__(256) void k_aggr(const __half* __restrict__ hf,
                                              const float* __restrict__ asrc,
                                              const float* __restrict__ adst,
                                              const float* __restrict__ bias,
                                              float* __restrict__ out, int n) {
    __shared__ float4 wbuf[8][32];
    __shared__ int    sbuf[8][32];
    int wid = threadIdx.x >> 5;
    int lane = threadIdx.x & 31;
    int node = (blockIdx.x * blockDim.x + threadIdx.x) >> 5;
    if (node >= n) return;

    int base = g_rowptr[node];
    int deg = g_rowptr[node + 1] - base;
    int h = lane >> 3;
    const float* wcol = (const float*)&wbuf[wid][0] + h;   // scalar w reads

    float4 ad = *(const float4*)(adst + (size_t)node * 4);

    float d0 = 0.f, d1 = 0.f, d2 = 0.f, d3 = 0.f;
    unsigned long long acc[4] = {0ull, 0ull, 0ull, 0ull};
    const __half* hlane = hf + lane * 8;

    for (int ib = 0; ib < deg; ib += 32) {
        int rem = min(32, deg - ib);
        {
            int sl = 0;
            float w0 = 0.f, w1 = 0.f, w2 = 0.f, w3 = 0.f;
            if (lane < rem) {
                sl = g_csr[base + ib + lane];
                float4 as = *(const float4*)(asrc + (size_t)sl * 4);
                w0 = __expf(lrelu(as.x + ad.x, 0.2f));
                w1 = __expf(lrelu(as.y + ad.y, 0.2f));
                w2 = __expf(lrelu(as.z + ad.z, 0.2f));
                w3 = __expf(lrelu(as.w + ad.w, 0.2f));
                d0 += w0; d1 += w1; d2 += w2; d3 += w3;
            }
            sbuf[wid][lane] = sl;
            wbuf[wid][lane] = make_float4(w0, w1, w2, w3);
        }
        __syncwarp();
        for (int j = 0; j < rem; j++) {
            int s = sbuf[wid][j];                 // LDS broadcast
            float wv = wcol[j * 4];               // scalar LDS (4-addr broadcast)
            unsigned long long w2p = pack2(wv, wv);
            uint4 hv = *(const uint4*)(hlane + (size_t)s * FOUT);  // 8 fp16
            ffma2(acc[0], w2p, h2f2(hv.x));
            ffma2(acc[1], w2p, h2f2(hv.y));
            ffma2(acc[2], w2p, h2f2(hv.z));
            ffma2(acc[3], w2p, h2f2(hv.w));
        }
        __syncwarp();
    }

    #pragma unroll
    for (int o = 16; o; o >>= 1) {
        d0 += __shfl_xor_sync(0xffffffffu, d0, o);
        d1 += __shfl_xor_sync(0xffffffffu, d1, o);
        d2 += __shfl_xor_sync(0xffffffffu, d2, o);
        d3 += __shfl_xor_sync(0xffffffffu, d3, o);
    }
    float i0 = d0 > 0.f ? 0.25f / d0 : 0.f;
    float i1 = d1 > 0.f ? 0.25f / d1 : 0.f;
    float i2 = d2 > 0.f ? 0.25f / d2 : 0.f;
    float i3 = d3 > 0.f ? 0.25f / d3 : 0.f;
    float inv = (h == 0) ? i0 : (h == 1) ? i1 : (h == 2) ? i2 : i3;
    unsigned long long inv2 = pack2(inv, inv);
    #pragma unroll
    for (int j = 0; j < 4; j++) mul2(acc[j], inv2);

    float v[8];
    #pragma unroll
    for (int j = 0; j < 4; j++) { v[2 * j] = lo2(acc[j]); v[2 * j + 1] = hi2(acc[j]); }
    #pragma unroll
    for (int j = 0; j < 8; j++) {
        v[j] += __shfl_xor_sync(0xffffffffu, v[j], 8);
        v[j] += __shfl_xor_sync(0xffffffffu, v[j], 16);
    }

    if (lane < 8) {
        const float4* bp = (const float4*)(bias + lane * 8);
        float4 bA = bp[0], bB = bp[1];
        float4 oA = make_float4(lrelu(v[0] + bA.x, 0.1f), lrelu(v[1] + bA.y, 0.1f),
                                lrelu(v[2] + bA.z, 0.1f), lrelu(v[3] + bA.w, 0.1f));
        float4 oB = make_float4(lrelu(v[4] + bB.x, 0.1f), lrelu(v[5] + bB.y, 0.1f),
                                lrelu(v[6] + bB.z, 0.1f), lrelu(v[7] + bB.w, 0.1f));
        float4* op = (float4*)(out + (size_t)node * CC + lane * 8);
        op[0] = oA;
        op[1] = oB;
    }
}

// ---------------------------------------------------------------------------
extern "C" void kernel_launch(void* const* d_in, const int* in_sizes, int n_in,
                              void* d_out, int out_size) {
    const float* x        = (const float*)d_in[0];
    const int*   ei       = (const int*)d_in[1];
    const float* W1       = (const float*)d_in[2];
    const float* A1       = (const float*)d_in[3];
    const float* att_src1 = (const float*)d_in[4];
    const float* att_dst1 = (const float*)d_in[5];
    const float* b1       = (const float*)d_in[6];
    const float* W2       = (const float*)d_in[7];
    const float* A2       = (const float*)d_in[8];
    const float* att_src2 = (const float*)d_in[9];
    const float* att_dst2 = (const float*)d_in[10];
    const float* b2       = (const float*)d_in[11];
    float* out = (float*)d_out;

    const int n = NN;
    const int eb = (EE + 255) / 256;

    __half* p_h;
    float *p_x2, *p_asrc, *p_adst, *p_vs1, *p_vd1, *p_vs2, *p_vd2;
    cudaGetSymbolAddress((void**)&p_h, g_h);
    cudaGetSymbolAddress((void**)&p_x2, g_x2);
    cudaGetSymbolAddress((void**)&p_asrc, g_asrc);
    cudaGetSymbolAddress((void**)&p_adst, g_adst);
    cudaGetSymbolAddress((void**)&p_vs1, g_vsrc1);
    cudaGetSymbolAddress((void**)&p_vd1, g_vdst1);
    cudaGetSymbolAddress((void**)&p_vs2, g_vsrc2);
    cudaGetSymbolAddress((void**)&p_vd2, g_vdst2);

    // #1 prep (detect + combines; counts are zeroed by previous run/init)
    k_prep<<<2, 256>>>(ei, A1, att_src1, att_dst1, A2, att_src2, att_dst2);
    // #2 histogram, #3 fused blocksum+scan
    k_hist<<<eb, 256>>>(ei);
    k_blocksum_scan<<<NB2, 256>>>();
    // #4 gemm1 (profiler captures launch #4; independent of CSR)
    k_gemm<128><<<(n + 63) / 64, 256>>>(x, W1, p_h, p_vs1, p_vd1, p_asrc, p_adst, n);
    // #5-#6 CSR finish (writeoff also re-zeroes counts for the next run)
    k_writeoff<<<NB2, 256>>>();
    k_scatter<<<eb, 256>>>(ei);
    // #7 layer-1 aggregation
    k_aggr<<<(n * 32 + 255) / 256, 256>>>(p_h, p_asrc, p_adst, b1, p_x2, n);
    // #8-#9 layer 2
    k_gemm<64><<<(n + 63) / 64, 256>>>(p_x2, W2, p_h, p_vs2, p_vd2, p_asrc, p_adst, n);
    k_aggr<<<(n * 32 + 255) / 256, 256>>>(p_h, p_asrc, p_adst, b2, out, n);
}

// round 16
// speedup vs baseline: 1.7531x; 1.0013x over previous
#include <cuda_runtime.h>
#include <cuda_fp16.h>
#include <cuda_bf16.h>
#include <cstdint>

// Problem constants
#define NN   50000
#define EE   800000
#define HH   4
#define CC   64
#define DD   4
#define FOUT 256   // H*C
#define NB2  ((NN + 255) / 256)   // 196 blocks of 256

// ---------------- scratch (device globals; no allocation allowed) ----------
__device__ __align__(16) __half g_h[(size_t)NN * FOUT];   // h messages, fp16
__device__ __align__(16) float g_x2[(size_t)NN * CC];     // layer-1 output
__device__ __align__(16) float g_asrc[NN * HH];
__device__ __align__(16) float g_adst[NN * HH];
// combined attention vectors, interleaved: vc[f*8 + h*2] = vsrc, +1 = vdst
__device__ __align__(16) float g_vc1[128 * HH * 2];
__device__ __align__(16) float g_vc2[64 * HH * 2];
__device__ int g_count[NN];      // zeroed by k_writeoff each run (+static init)
__device__ int g_off[NN];
__device__ int g_rowptr[NN + 1];
__device__ int g_csr[EE];
__device__ int g_is64;
__device__ int g_bsum[256];
__device__ int g_bpre[256];
__device__ int g_done;           // blocksum completion counter (self-resetting)

__device__ __forceinline__ float lrelu(float v, float s) { return v >= 0.f ? v : s * v; }

// packed f32x2 helpers (sm_103a)
__device__ __forceinline__ unsigned long long pack2(float lo, float hi) {
    unsigned long long r;
    asm("mov.b64 %0, {%1, %2};" : "=l"(r) : "f"(lo), "f"(hi));
    return r;
}
__device__ __forceinline__ void ffma2(unsigned long long& d, unsigned long long a,
                                      unsigned long long b) {
    asm("fma.rn.f32x2 %0, %1, %2, %0;" : "+l"(d) : "l"(a), "l"(b));
}
__device__ __forceinline__ void mul2(unsigned long long& d, unsigned long long a) {
    asm("mul.rn.f32x2 %0, %0, %1;" : "+l"(d) : "l"(a));
}
__device__ __forceinline__ float lo2(unsigned long long v) {
    float a, b; asm("mov.b64 {%0, %1}, %2;" : "=f"(a), "=f"(b) : "l"(v)); return a;
}
__device__ __forceinline__ float hi2(unsigned long long v) {
    float a, b; asm("mov.b64 {%0, %1}, %2;" : "=f"(a), "=f"(b) : "l"(v)); return b;
}
// half2 word -> packed f32x2
__device__ __forceinline__ unsigned long long h2f2(uint32_t u) {
    __half2 h = *reinterpret_cast<__half2*>(&u);
    float2 f = __half22float2(h);
    return pack2(f.x, f.y);
}
// pack (lo=a, hi=b) into fp16x2 word
__device__ __forceinline__ uint32_t hpack(float a, float b) {
    uint32_t r;
    asm("cvt.rn.f16x2.f32 %0, %1, %2;" : "=r"(r) : "f"(b), "f"(a));
    return r;
}

// fp16 tensor-core mma: D(16x8,f32) += A(16x16,f16,row) * B(16x8,f16,col)
__device__ __forceinline__ void mma_f16(float& d0, float& d1, float& d2, float& d3,
                                        uint32_t a0, uint32_t a1, uint32_t a2, uint32_t a3,
                                        uint32_t b0, uint32_t b1) {
    asm("mma.sync.aligned.m16n8k16.row.col.f32.f16.f16.f32 "
        "{%0,%1,%2,%3}, {%4,%5,%6,%7}, {%8,%9}, {%0,%1,%2,%3};"
        : "+f"(d0), "+f"(d1), "+f"(d2), "+f"(d3)
        : "r"(a0), "r"(a1), "r"(a2), "r"(a3), "r"(b0), "r"(b1));
}

// ---------------- prep: dtype detect + both A*att combines (2 blocks) ------
__global__ __launch_bounds__(256) void k_prep(const int* ei_words,
                                              const float* __restrict__ A1,
                                              const float* __restrict__ as1,
                                              const float* __restrict__ ad1,
                                              const float* __restrict__ A2,
                                              const float* __restrict__ as2,
                                              const float* __restrict__ ad2) {
    int i = blockIdx.x * 256 + threadIdx.x;
    if (i == 0) {
        int nz = 0;
        for (int j = 0; j < 64; j++)
            if (ei_words[2 * j + 1] != 0) nz++;
        g_is64 = (nz == 0) ? 1 : 0;
    }
    if (i < 128 * HH) {
        int f = i >> 2, h = i & 3;
        float s1 = 0.f, s2 = 0.f;
        #pragma unroll
        for (int d = 0; d < DD; d++) {
            float a = A1[f * (HH * DD) + h * DD + d];
            s1 += a * as1[h * DD + d];
            s2 += a * ad1[h * DD + d];
        }
        g_vc1[f * 8 + h * 2]     = s1;
        g_vc1[f * 8 + h * 2 + 1] = s2;
    }
    if (i < 64 * HH) {
        int f = i >> 2, h = i & 3;
        float s1 = 0.f, s2 = 0.f;
        #pragma unroll
        for (int d = 0; d < DD; d++) {
            float a = A2[f * (HH * DD) + h * DD + d];
            s1 += a * as2[h * DD + d];
            s2 += a * ad2[h * DD + d];
        }
        g_vc2[f * 8 + h * 2]     = s1;
        g_vc2[f * 8 + h * 2 + 1] = s2;
    }
}

// ---- histogram: 2 edges/thread, vectorized index loads --------------------
__global__ void k_hist(const int* ei_words) {
    int e2 = blockIdx.x * blockDim.x + threadIdx.x;
    int e = 2 * e2;
    if (e >= EE) return;
    int d0, d1;
    if (g_is64) {
        // dst elements at int64 index EE+e, EE+e+1 -> words 2*(EE+e) .. +3
        int4 v = *(const int4*)&ei_words[2 * ((size_t)EE + e)];
        d0 = v.x; d1 = v.z;
    } else {
        int2 v = *(const int2*)&ei_words[(size_t)EE + e];
        d0 = v.x; d1 = v.y;
    }
    atomicAdd(&g_count[d0], 1);
    atomicAdd(&g_count[d1], 1);
}

// ---- fused blocksum + scan-of-partials (last-block-done pattern) ----------
__global__ __launch_bounds__(256) void k_blocksum_scan() {
    __shared__ int sh[256];
    __shared__ bool last;
    int tid = threadIdx.x;
    int i = blockIdx.x * 256 + tid;
    int v = (i < NN) ? g_count[i] : 0;
    #pragma unroll
    for (int o = 16; o; o >>= 1) v += __shfl_xor_sync(0xffffffffu, v, o);
    if ((tid & 31) == 0) sh[tid >> 5] = v;
    __syncthreads();
    if (tid == 0) {
        int s = 0;
        #pragma unroll
        for (int j = 0; j < 8; j++) s += sh[j];
        g_bsum[blockIdx.x] = s;
        __threadfence();
        int prev = atomicAdd(&g_done, 1);
        last = (prev == (int)gridDim.x - 1);
    }
    __syncthreads();
    if (last) {
        __threadfence();   // acquire all blocks' g_bsum writes
        int nb = gridDim.x;
        int b = (tid < nb) ? g_bsum[tid] : 0;
        sh[tid] = b;
        __syncthreads();
        for (int o = 1; o < 256; o <<= 1) {
            int u = (tid >= o) ? sh[tid - o] : 0;
            __syncthreads();
            sh[tid] += u;
            __syncthreads();
        }
        if (tid < nb) g_bpre[tid] = sh[tid] - b;  // exclusive
        if (tid == 0) g_done = 0;                 // reset for next run
    }
}

__global__ __launch_bounds__(256) void k_writeoff() {
    __shared__ int wpre[8];
    int t = threadIdx.x;
    int lane = t & 31, w = t >> 5;
    int i = blockIdx.x * 256 + t;
    int c = (i < NN) ? g_count[i] : 0;
    int v = c;
    #pragma unroll
    for (int o = 1; o < 32; o <<= 1) {
        int u = __shfl_up_sync(0xffffffffu, v, o);
        if (lane >= o) v += u;
    }
    if (lane == 31) wpre[w] = v;
    __syncthreads();
    if (t == 0) {
        int run = 0;
        #pragma unroll
        for (int j = 0; j < 8; j++) { int tmp = wpre[j]; wpre[j] = run; run += tmp; }
    }
    __syncthreads();
    int excl = v - c + wpre[w] + g_bpre[blockIdx.x];
    if (i < NN) {
        g_rowptr[i] = excl;
        g_off[i] = excl;
        g_count[i] = 0;    // counts are dead: re-zero for the next run
        if (i == NN - 1) g_rowptr[NN] = excl + c;
    }
}

// ---- scatter: 2 edges/thread, vectorized index loads ----------------------
__global__ void k_scatter(const int* ei_words) {
    int e2 = blockIdx.x * blockDim.x + threadIdx.x;
    int e = 2 * e2;
    if (e >= EE) return;
    int s0, s1, d0, d1;
    if (g_is64) {
        int4 sv = *(const int4*)&ei_words[2 * (size_t)e];
        int4 dv = *(const int4*)&ei_words[2 * ((size_t)EE + e)];
        s0 = sv.x; s1 = sv.z; d0 = dv.x; d1 = dv.z;
    } else {
        int2 sv = *(const int2*)&ei_words[(size_t)e];
        int2 dv = *(const int2*)&ei_words[(size_t)EE + e];
        s0 = sv.x; s1 = sv.y; d0 = dv.x; d1 = dv.y;
    }
    g_csr[atomicAdd(&g_off[d0], 1)] = s0;
    g_csr[atomicAdd(&g_off[d1], 1)] = s1;
}

// ---------------- fp16 tensor-core GEMM (m16n8k16) + W reg prefetch --------
// 256 thr = 8 warps; block tile 64 rows x 256 cols; warp tile 32 x 64.
// xs: half2 words, stride XSTW = FIN/2+4 (== 4 mod 32): A-frag LDS clean.
// wsT: W chunk transposed [col][kpair], stride 9 (coprime 32): STS clean.
// Alpha epilogue fully packed: (s1,s2) accumulated as one f32x2 register,
// (vsrc,vdst) read as one float2 from interleaved smem copy.
template <int FIN>
__global__ __launch_bounds__(256, 2) void k_gemm(const float* __restrict__ x,
                                                 const float* __restrict__ W,
                                                 __half* __restrict__ hout,
                                                 const float* __restrict__ vc,
                                                 float* __restrict__ asrc,
                                                 float* __restrict__ adst, int n) {
    constexpr int KW = FIN / 2;        // half2 words per row of x
    constexpr int XSTW = KW + 4;       // == 4 mod 32
    constexpr int KST2 = 9;            // half2 words per wsT column
    __shared__ uint32_t xs[64 * XSTW];
    __shared__ uint32_t wsT[256 * KST2];
    __shared__ float svc[FIN * 8];     // interleaved (vsrc,vdst) pairs
    int tid = threadIdx.x;
    int lane = tid & 31;
    int w = tid >> 5;
    int row0 = blockIdx.x * 64;
    int mrow = (w >> 2) * 32;
    int ncol = (w & 3) * 64;
    int l4 = lane >> 2;       // 0..7
    int lk = lane & 3;        // 0..3

    // load x tile -> fp16 pairs
    for (int idx = tid; idx < 64 * KW; idx += 256) {
        int r = idx / KW, kp = idx - r * KW;
        int row = row0 + r;
        float v0 = 0.f, v1 = 0.f;
        if (row < n) {
            const float2 xv = *(const float2*)&x[(size_t)row * FIN + 2 * kp];
            v0 = xv.x; v1 = xv.y;
        }
        xs[r * XSTW + kp] = hpack(v0, v1);
    }
    // stage combined attention vectors
    for (int idx = tid; idx < FIN * 8; idx += 256) svc[idx] = vc[idx];

    // prefetch chunk 0 of W: rows 0..15, col tid
    float wreg[16];
    #pragma unroll
    for (int i = 0; i < 16; i++) wreg[i] = W[(size_t)i * FOUT + tid];

    float d[2][8][4];
    #pragma unroll
    for (int t = 0; t < 2; t++)
        #pragma unroll
        for (int j = 0; j < 8; j++)
            #pragma unroll
            for (int q = 0; q < 4; q++) d[t][j][q] = 0.f;

    for (int kc = 0; kc < FIN; kc += 16) {
        __syncthreads();   // wsT free (first iter: xs/svc writes ordered)
        #pragma unroll
        for (int i = 0; i < 8; i++)
            wsT[tid * KST2 + i] = hpack(wreg[2 * i], wreg[2 * i + 1]);
        __syncthreads();

        // prefetch next chunk while computing this one
        if (kc + 16 < FIN) {
            #pragma unroll
            for (int i = 0; i < 16; i++)
                wreg[i] = W[(size_t)(kc + 16 + i) * FOUT + tid];
        }

        // B fragments (shared by both m-tiles)
        uint32_t b0[8], b1[8];
        #pragma unroll
        for (int j = 0; j < 8; j++) {
            int col = ncol + j * 8 + l4;
            b0[j] = wsT[col * KST2 + lk];
            b1[j] = wsT[col * KST2 + lk + 4];
        }
        int kw = (kc >> 1) + lk;
        #pragma unroll
        for (int t = 0; t < 2; t++) {
            int rb = mrow + t * 16 + l4;
            uint32_t a0 = xs[rb * XSTW + kw];
            uint32_t a1 = xs[(rb + 8) * XSTW + kw];
            uint32_t a2 = xs[rb * XSTW + kw + 4];
            uint32_t a3 = xs[(rb + 8) * XSTW + kw + 4];
            #pragma unroll
            for (int j = 0; j < 8; j++)
                mma_f16(d[t][j][0], d[t][j][1], d[t][j][2], d[t][j][3],
                        a0, a1, a2, a3, b0[j], b1[j]);
        }
    }

    // store D as fp16: thread owns fp16x2 word at cols (c, c+1), rows rb, rb+8
    #pragma unroll
    for (int t = 0; t < 2; t++) {
        int r0 = row0 + mrow + t * 16 + l4;
        #pragma unroll
        for (int j = 0; j < 8; j++) {
            int c = ncol + j * 8 + lk * 2;
            uint32_t w0 = hpack(d[t][j][0], d[t][j][1]);
            uint32_t w1 = hpack(d[t][j][2], d[t][j][3]);
            if (r0 < n)     *(uint32_t*)&hout[(size_t)r0 * FOUT + c] = w0;
            if (r0 + 8 < n) *(uint32_t*)&hout[(size_t)(r0 + 8) * FOUT + c] = w1;
        }
    }

    // alpha: 256 threads = 64 rows x 4 heads; packed f32x2 accumulation of
    // (alpha_src, alpha_dst) with interleaved (vsrc,vdst) pairs from smem.
    {
        int r = tid >> 2, h = tid & 3;
        int row = row0 + r;
        if (row < n) {
            unsigned long long acc = 0ull;
            const float2* vp = (const float2*)&svc[h * 2];  // stride 4 float2
            #pragma unroll 4
            for (int kp = 0; kp < KW; kp++) {
                uint32_t u = xs[r * XSTW + kp];
                __half2 hh = *reinterpret_cast<__half2*>(&u);
                float2 f = __half22float2(hh);
                float2 c0 = vp[(2 * kp) * 4];
                float2 c1 = vp[(2 * kp + 1) * 4];
                ffma2(acc, pack2(f.x, f.x), pack2(c0.x, c0.y));
                ffma2(acc, pack2(f.y, f.y), pack2(c1.x, c1.y));
            }
            asrc[row * HH + h] = lo2(acc);
            adst[row * HH + h] = hi2(acc);
        }
    }
}

// ---------------- per-dst-node softmax + weighted aggregation (1 warp/node)
// No-max softmax (|e| bounded ~0.5 by construction). Lane l owns channels
// [8l, 8l+8); one LDG.128 = 8 fp16 per edge per lane; fp32 accumulation.
__global__ __launch_bounds__(256) void k_aggr(const __half* __restrict__ hf,
                                              const float* __restrict__ asrc,
                                              const float* __restrict__ adst,
                                              const float* __restrict__ bias,
                                              float* __restrict__ out, int n) {
    __shared__ float4 wbuf[8][32];
    __shared__ int    sbuf[8][32];
    int wid = threadIdx.x >> 5;
    int lane = threadIdx.x & 31;
    int node = (blockIdx.x * blockDim.x + threadIdx.x) >> 5;
    if (node >= n) return;

    int base = g_rowptr[node];
    int deg = g_rowptr[node + 1] - base;
    int h = lane >> 3;
    const float* wcol = (const float*)&wbuf[wid][0] + h;   // scalar w reads

    float4 ad = *(const float4*)(adst + (size_t)node * 4);

    float d0 = 0.f, d1 = 0.f, d2 = 0.f, d3 = 0.f;
    unsigned long long acc[4] = {0ull, 0ull, 0ull, 0ull};
    const __half* hlane = hf + lane * 8;

    for (int ib = 0; ib < deg; ib += 32) {
        int rem = min(32, deg - ib);
        {
            int sl = 0;
            float w0 = 0.f, w1 = 0.f, w2 = 0.f, w3 = 0.f;
            if (lane < rem) {
                sl = g_csr[base + ib + lane];
                float4 as = *(const float4*)(asrc + (size_t)sl * 4);
                w0 = __expf(lrelu(as.x + ad.x, 0.2f));
                w1 = __expf(lrelu(as.y + ad.y, 0.2f));
                w2 = __expf(lrelu(as.z + ad.z, 0.2f));
                w3 = __expf(lrelu(as.w + ad.w, 0.2f));
                d0 += w0; d1 += w1; d2 += w2; d3 += w3;
            }
            sbuf[wid][lane] = sl;
            wbuf[wid][lane] = make_float4(w0, w1, w2, w3);
        }
        __syncwarp();
        for (int j = 0; j < rem; j++) {
            int s = sbuf[wid][j];                 // LDS broadcast
            float wv = wcol[j * 4];               // scalar LDS (4-addr broadcast)
            unsigned long long w2p = pack2(wv, wv);
            uint4 hv = *(const uint4*)(hlane + (size_t)s * FOUT);  // 8 fp16
            ffma2(acc[0], w2p, h2f2(hv.x));
            ffma2(acc[1], w2p, h2f2(hv.y));
            ffma2(acc[2], w2p, h2f2(hv.z));
            ffma2(acc[3], w2p, h2f2(hv.w));
        }
        __syncwarp();
    }

    #pragma unroll
    for (int o = 16; o; o >>= 1) {
        d0 += __shfl_xor_sync(0xffffffffu, d0, o);
        d1 += __shfl_xor_sync(0xffffffffu, d1, o);
        d2 += __shfl_xor_sync(0xffffffffu, d2, o);
        d3 += __shfl_xor_sync(0xffffffffu, d3, o);
    }
    float i0 = d0 > 0.f ? 0.25f / d0 : 0.f;
    float i1 = d1 > 0.f ? 0.25f / d1 : 0.f;
    float i2 = d2 > 0.f ? 0.25f / d2 : 0.f;
    float i3 = d3 > 0.f ? 0.25f / d3 : 0.f;
    float inv = (h == 0) ? i0 : (h == 1) ? i1 : (h == 2) ? i2 : i3;
    unsigned long long inv2 = pack2(inv, inv);
    #pragma unroll
    for (int j = 0; j < 4; j++) mul2(acc[j], inv2);

    float v[8];
    #pragma unroll
    for (int j = 0; j < 4; j++) { v[2 * j] = lo2(acc[j]); v[2 * j + 1] = hi2(acc[j]); }
    #pragma unroll
    for (int j = 0; j < 8; j++) {
        v[j] += __shfl_xor_sync(0xffffffffu, v[j], 8);
        v[j] += __shfl_xor_sync(0xffffffffu, v[j], 16);
    }

    if (lane < 8) {
        const float4* bp = (const float4*)(bias + lane * 8);
        float4 bA = bp[0], bB = bp[1];
        float4 oA = make_float4(lrelu(v[0] + bA.x, 0.1f), lrelu(v[1] + bA.y, 0.1f),
                                lrelu(v[2] + bA.z, 0.1f), lrelu(v[3] + bA.w, 0.1f));
        float4 oB = make_float4(lrelu(v[4] + bB.x, 0.1f), lrelu(v[5] + bB.y, 0.1f),
                                lrelu(v[6] + bB.z, 0.1f), lrelu(v[7] + bB.w, 0.1f));
        float4* op = (float4*)(out + (size_t)node * CC + lane * 8);
        op[0] = oA;
        op[1] = oB;
    }
}

// ---------------------------------------------------------------------------
extern "C" void kernel_launch(void* const* d_in, const int* in_sizes, int n_in,
                              void* d_out, int out_size) {
    const float* x        = (const float*)d_in[0];
    const int*   ei       = (const int*)d_in[1];
    const float* W1       = (const float*)d_in[2];
    const float* A1       = (const float*)d_in[3];
    const float* att_src1 = (const float*)d_in[4];
    const float* att_dst1 = (const float*)d_in[5];
    const float* b1       = (const float*)d_in[6];
    const float* W2       = (const float*)d_in[7];
    const float* A2       = (const float*)d_in[8];
    const float* att_src2 = (const float*)d_in[9];
    const float* att_dst2 = (const float*)d_in[10];
    const float* b2       = (const float*)d_in[11];
    float* out = (float*)d_out;

    const int n = NN;
    const int eb2 = (EE / 2 + 255) / 256;

    __half* p_h;
    float *p_x2, *p_asrc, *p_adst, *p_vc1, *p_vc2;
    cudaGetSymbolAddress((void**)&p_h, g_h);
    cudaGetSymbolAddress((void**)&p_x2, g_x2);
    cudaGetSymbolAddress((void**)&p_asrc, g_asrc);
    cudaGetSymbolAddress((void**)&p_adst, g_adst);
    cudaGetSymbolAddress((void**)&p_vc1, g_vc1);
    cudaGetSymbolAddress((void**)&p_vc2, g_vc2);

    // #1 prep (detect + combines; counts zeroed by previous run/static init)
    k_prep<<<2, 256>>>(ei, A1, att_src1, att_dst1, A2, att_src2, att_dst2);
    // #2 histogram (2 edges/thread), #3 fused blocksum+scan
    k_hist<<<eb2, 256>>>(ei);
    k_blocksum_scan<<<NB2, 256>>>();
    // #4 gemm1 (profiler captures launch #4; independent of CSR)
    k_gemm<128><<<(n + 63) / 64, 256>>>(x, W1, p_h, p_vc1, p_asrc, p_adst, n);
    // #5-#6 CSR finish (writeoff re-zeroes counts for the next run)
    k_writeoff<<<NB2, 256>>>();
    k_scatter<<<eb2, 256>>>(ei);
    // #7 layer-1 aggregation
    k_aggr<<<(n * 32 + 255) / 256, 256>>>(p_h, p_asrc, p_adst, b1, p_x2, n);
    // #8-#9 layer 2
    k_gemm<64><<<(n + 63) / 64, 256>>>(p_x2, W2, p_h, p_vc2, p_asrc, p_adst, n);
    k_aggr<<<(n * 32 + 255) / 256, 256>>>(p_h, p_asrc, p_adst, b2, out, n);
}

// round 17
// speedup vs baseline: 1.8635x; 1.0629x over previous
#include <cuda_runtime.h>
#include <cuda_fp16.h>
#include <cuda_bf16.h>
#include <cstdint>

// Problem constants
#define NN   50000
#define EE   800000
#define HH   4
#define CC   64
#define DD   4
#define FOUT 256   // H*C
#define NB2  ((NN + 255) / 256)   // 196 blocks of 256

// ---------------- scratch (device globals; no allocation allowed) ----------
__device__ __align__(16) __half g_h[(size_t)NN * FOUT];   // h messages, fp16
__device__ __align__(16) float g_x2[(size_t)NN * CC];     // layer-1 output
__device__ __align__(16) float g_asrc[NN * HH];
__device__ __align__(16) float g_adst[NN * HH];
// combined attention vectors, interleaved: vc[f*8 + h*2] = vsrc, +1 = vdst
__device__ __align__(16) float g_vc1[128 * HH * 2];
__device__ __align__(16) float g_vc2[64 * HH * 2];
__device__ int g_count[NN];      // zeroed by k_writeoff each run (+static init)
__device__ int g_off[NN];
__device__ int g_rowptr[NN + 1];
__device__ int g_csr[EE];
__device__ int g_is64;
__device__ int g_bsum[256];
__device__ int g_bpre[256];
__device__ int g_done;           // blocksum completion counter (self-resetting)

__device__ __forceinline__ float lrelu(float v, float s) { return v >= 0.f ? v : s * v; }

// packed f32x2 helpers (sm_103a)
__device__ __forceinline__ unsigned long long pack2(float lo, float hi) {
    unsigned long long r;
    asm("mov.b64 %0, {%1, %2};" : "=l"(r) : "f"(lo), "f"(hi));
    return r;
}
__device__ __forceinline__ void ffma2(unsigned long long& d, unsigned long long a,
                                      unsigned long long b) {
    asm("fma.rn.f32x2 %0, %1, %2, %0;" : "+l"(d) : "l"(a), "l"(b));
}
__device__ __forceinline__ void mul2(unsigned long long& d, unsigned long long a) {
    asm("mul.rn.f32x2 %0, %0, %1;" : "+l"(d) : "l"(a));
}
__device__ __forceinline__ float lo2(unsigned long long v) {
    float a, b; asm("mov.b64 {%0, %1}, %2;" : "=f"(a), "=f"(b) : "l"(v)); return a;
}
__device__ __forceinline__ float hi2(unsigned long long v) {
    float a, b; asm("mov.b64 {%0, %1}, %2;" : "=f"(a), "=f"(b) : "l"(v)); return b;
}
// half2 word -> packed f32x2
__device__ __forceinline__ unsigned long long h2f2(uint32_t u) {
    __half2 h = *reinterpret_cast<__half2*>(&u);
    float2 f = __half22float2(h);
    return pack2(f.x, f.y);
}
// pack (lo=a, hi=b) into fp16x2 word
__device__ __forceinline__ uint32_t hpack(float a, float b) {
    uint32_t r;
    asm("cvt.rn.f16x2.f32 %0, %1, %2;" : "=r"(r) : "f"(b), "f"(a));
    return r;
}

// fp16 tensor-core mma: D(16x8,f32) += A(16x16,f16,row) * B(16x8,f16,col)
__device__ __forceinline__ void mma_f16(float& d0, float& d1, float& d2, float& d3,
                                        uint32_t a0, uint32_t a1, uint32_t a2, uint32_t a3,
                                        uint32_t b0, uint32_t b1) {
    asm("mma.sync.aligned.m16n8k16.row.col.f32.f16.f16.f32 "
        "{%0,%1,%2,%3}, {%4,%5,%6,%7}, {%8,%9}, {%0,%1,%2,%3};"
        : "+f"(d0), "+f"(d1), "+f"(d2), "+f"(d3)
        : "r"(a0), "r"(a1), "r"(a2), "r"(a3), "r"(b0), "r"(b1));
}

// ---------------- prep: dtype detect + both A*att combines (2 blocks) ------
__global__ __launch_bounds__(256) void k_prep(const int* ei_words,
                                              const float* __restrict__ A1,
                                              const float* __restrict__ as1,
                                              const float* __restrict__ ad1,
                                              const float* __restrict__ A2,
                                              const float* __restrict__ as2,
                                              const float* __restrict__ ad2) {
    int i = blockIdx.x * 256 + threadIdx.x;
    if (i == 0) {
        int nz = 0;
        for (int j = 0; j < 64; j++)
            if (ei_words[2 * j + 1] != 0) nz++;
        g_is64 = (nz == 0) ? 1 : 0;
    }
    if (i < 128 * HH) {
        int f = i >> 2, h = i & 3;
        float s1 = 0.f, s2 = 0.f;
        #pragma unroll
        for (int d = 0; d < DD; d++) {
            float a = A1[f * (HH * DD) + h * DD + d];
            s1 += a * as1[h * DD + d];
            s2 += a * ad1[h * DD + d];
        }
        g_vc1[f * 8 + h * 2]     = s1;
        g_vc1[f * 8 + h * 2 + 1] = s2;
    }
    if (i < 64 * HH) {
        int f = i >> 2, h = i & 3;
        float s1 = 0.f, s2 = 0.f;
        #pragma unroll
        for (int d = 0; d < DD; d++) {
            float a = A2[f * (HH * DD) + h * DD + d];
            s1 += a * as2[h * DD + d];
            s2 += a * ad2[h * DD + d];
        }
        g_vc2[f * 8 + h * 2]     = s1;
        g_vc2[f * 8 + h * 2 + 1] = s2;
    }
}

// ---- histogram: 2 edges/thread, vectorized index loads --------------------
__global__ void k_hist(const int* ei_words) {
    int e2 = blockIdx.x * blockDim.x + threadIdx.x;
    int e = 2 * e2;
    if (e >= EE) return;
    int d0, d1;
    if (g_is64) {
        int4 v = *(const int4*)&ei_words[2 * ((size_t)EE + e)];
        d0 = v.x; d1 = v.z;
    } else {
        int2 v = *(const int2*)&ei_words[(size_t)EE + e];
        d0 = v.x; d1 = v.y;
    }
    atomicAdd(&g_count[d0], 1);
    atomicAdd(&g_count[d1], 1);
}

// ---- fused blocksum + scan-of-partials (last-block-done pattern) ----------
__global__ __launch_bounds__(256) void k_blocksum_scan() {
    __shared__ int sh[256];
    __shared__ bool last;
    int tid = threadIdx.x;
    int i = blockIdx.x * 256 + tid;
    int v = (i < NN) ? g_count[i] : 0;
    #pragma unroll
    for (int o = 16; o; o >>= 1) v += __shfl_xor_sync(0xffffffffu, v, o);
    if ((tid & 31) == 0) sh[tid >> 5] = v;
    __syncthreads();
    if (tid == 0) {
        int s = 0;
        #pragma unroll
        for (int j = 0; j < 8; j++) s += sh[j];
        g_bsum[blockIdx.x] = s;
        __threadfence();
        int prev = atomicAdd(&g_done, 1);
        last = (prev == (int)gridDim.x - 1);
    }
    __syncthreads();
    if (last) {
        __threadfence();   // acquire all blocks' g_bsum writes
        int nb = gridDim.x;
        int b = (tid < nb) ? g_bsum[tid] : 0;
        sh[tid] = b;
        __syncthreads();
        for (int o = 1; o < 256; o <<= 1) {
            int u = (tid >= o) ? sh[tid - o] : 0;
            __syncthreads();
            sh[tid] += u;
            __syncthreads();
        }
        if (tid < nb) g_bpre[tid] = sh[tid] - b;  // exclusive
        if (tid == 0) g_done = 0;                 // reset for next run
    }
}

__global__ __launch_bounds__(256) void k_writeoff() {
    __shared__ int wpre[8];
    int t = threadIdx.x;
    int lane = t & 31, w = t >> 5;
    int i = blockIdx.x * 256 + t;
    int c = (i < NN) ? g_count[i] : 0;
    int v = c;
    #pragma unroll
    for (int o = 1; o < 32; o <<= 1) {
        int u = __shfl_up_sync(0xffffffffu, v, o);
        if (lane >= o) v += u;
    }
    if (lane == 31) wpre[w] = v;
    __syncthreads();
    if (t == 0) {
        int run = 0;
        #pragma unroll
        for (int j = 0; j < 8; j++) { int tmp = wpre[j]; wpre[j] = run; run += tmp; }
    }
    __syncthreads();
    int excl = v - c + wpre[w] + g_bpre[blockIdx.x];
    if (i < NN) {
        g_rowptr[i] = excl;
        g_off[i] = excl;
        g_count[i] = 0;    // counts are dead: re-zero for the next run
        if (i == NN - 1) g_rowptr[NN] = excl + c;
    }
}

// ---- scatter: 2 edges/thread, vectorized index loads ----------------------
__global__ void k_scatter(const int* ei_words) {
    int e2 = blockIdx.x * blockDim.x + threadIdx.x;
    int e = 2 * e2;
    if (e >= EE) return;
    int s0, s1, d0, d1;
    if (g_is64) {
        int4 sv = *(const int4*)&ei_words[2 * (size_t)e];
        int4 dv = *(const int4*)&ei_words[2 * ((size_t)EE + e)];
        s0 = sv.x; s1 = sv.z; d0 = dv.x; d1 = dv.z;
    } else {
        int2 sv = *(const int2*)&ei_words[(size_t)e];
        int2 dv = *(const int2*)&ei_words[(size_t)EE + e];
        s0 = sv.x; s1 = sv.y; d0 = dv.x; d1 = dv.y;
    }
    g_csr[atomicAdd(&g_off[d0], 1)] = s0;
    g_csr[atomicAdd(&g_off[d1], 1)] = s1;
}

// ---------------- fp16 tensor-core GEMM (m16n8k16) + W reg prefetch --------
// 256 thr = 8 warps; block tile 64 rows x 256 cols; warp tile 32 x 64.
// xs: half2 words, stride XSTW = FIN/2+4 (== 4 mod 32): A-frag LDS clean.
// wsT: W chunk transposed [col][kpair], stride 9 (coprime 32): STS clean.
template <int FIN>
__global__ __launch_bounds__(256, 2) void k_gemm(const float* __restrict__ x,
                                                 const float* __restrict__ W,
                                                 __half* __restrict__ hout,
                                                 const float* __restrict__ vc,
                                                 float* __restrict__ asrc,
                                                 float* __restrict__ adst, int n) {
    constexpr int KW = FIN / 2;        // half2 words per row of x
    constexpr int XSTW = KW + 4;       // == 4 mod 32
    constexpr int KST2 = 9;            // half2 words per wsT column
    __shared__ uint32_t xs[64 * XSTW];
    __shared__ uint32_t wsT[256 * KST2];
    __shared__ float svc[FIN * 8];     // interleaved (vsrc,vdst) pairs
    int tid = threadIdx.x;
    int lane = tid & 31;
    int w = tid >> 5;
    int row0 = blockIdx.x * 64;
    int mrow = (w >> 2) * 32;
    int ncol = (w & 3) * 64;
    int l4 = lane >> 2;       // 0..7
    int lk = lane & 3;        // 0..3

    // load x tile -> fp16 pairs
    for (int idx = tid; idx < 64 * KW; idx += 256) {
        int r = idx / KW, kp = idx - r * KW;
        int row = row0 + r;
        float v0 = 0.f, v1 = 0.f;
        if (row < n) {
            const float2 xv = *(const float2*)&x[(size_t)row * FIN + 2 * kp];
            v0 = xv.x; v1 = xv.y;
        }
        xs[r * XSTW + kp] = hpack(v0, v1);
    }
    // stage combined attention vectors
    for (int idx = tid; idx < FIN * 8; idx += 256) svc[idx] = vc[idx];

    // prefetch chunk 0 of W: rows 0..15, col tid
    float wreg[16];
    #pragma unroll
    for (int i = 0; i < 16; i++) wreg[i] = W[(size_t)i * FOUT + tid];

    float d[2][8][4];
    #pragma unroll
    for (int t = 0; t < 2; t++)
        #pragma unroll
        for (int j = 0; j < 8; j++)
            #pragma unroll
            for (int q = 0; q < 4; q++) d[t][j][q] = 0.f;

    for (int kc = 0; kc < FIN; kc += 16) {
        __syncthreads();   // wsT free (first iter: xs/svc writes ordered)
        #pragma unroll
        for (int i = 0; i < 8; i++)
            wsT[tid * KST2 + i] = hpack(wreg[2 * i], wreg[2 * i + 1]);
        __syncthreads();

        // prefetch next chunk while computing this one
        if (kc + 16 < FIN) {
            #pragma unroll
            for (int i = 0; i < 16; i++)
                wreg[i] = W[(size_t)(kc + 16 + i) * FOUT + tid];
        }

        // B fragments (shared by both m-tiles)
        uint32_t b0[8], b1[8];
        #pragma unroll
        for (int j = 0; j < 8; j++) {
            int col = ncol + j * 8 + l4;
            b0[j] = wsT[col * KST2 + lk];
            b1[j] = wsT[col * KST2 + lk + 4];
        }
        int kw = (kc >> 1) + lk;
        #pragma unroll
        for (int t = 0; t < 2; t++) {
            int rb = mrow + t * 16 + l4;
            uint32_t a0 = xs[rb * XSTW + kw];
            uint32_t a1 = xs[(rb + 8) * XSTW + kw];
            uint32_t a2 = xs[rb * XSTW + kw + 4];
            uint32_t a3 = xs[(rb + 8) * XSTW + kw + 4];
            #pragma unroll
            for (int j = 0; j < 8; j++)
                mma_f16(d[t][j][0], d[t][j][1], d[t][j][2], d[t][j][3],
                        a0, a1, a2, a3, b0[j], b1[j]);
        }
    }

    // store D as fp16: thread owns fp16x2 word at cols (c, c+1), rows rb, rb+8
    #pragma unroll
    for (int t = 0; t < 2; t++) {
        int r0 = row0 + mrow + t * 16 + l4;
        #pragma unroll
        for (int j = 0; j < 8; j++) {
            int c = ncol + j * 8 + lk * 2;
            uint32_t w0 = hpack(d[t][j][0], d[t][j][1]);
            uint32_t w1 = hpack(d[t][j][2], d[t][j][3]);
            if (r0 < n)     *(uint32_t*)&hout[(size_t)r0 * FOUT + c] = w0;
            if (r0 + 8 < n) *(uint32_t*)&hout[(size_t)(r0 + 8) * FOUT + c] = w1;
        }
    }

    // alpha: 256 threads = 64 rows x 4 heads; packed f32x2 accumulation
    {
        int r = tid >> 2, h = tid & 3;
        int row = row0 + r;
        if (row < n) {
            unsigned long long acc = 0ull;
            const float2* vp = (const float2*)&svc[h * 2];  // stride 4 float2
            #pragma unroll 4
            for (int kp = 0; kp < KW; kp++) {
                uint32_t u = xs[r * XSTW + kp];
                __half2 hh = *reinterpret_cast<__half2*>(&u);
                float2 f = __half22float2(hh);
                float2 c0 = vp[(2 * kp) * 4];
                float2 c1 = vp[(2 * kp + 1) * 4];
                ffma2(acc, pack2(f.x, f.x), pack2(c0.x, c0.y));
                ffma2(acc, pack2(f.y, f.y), pack2(c1.x, c1.y));
            }
            asrc[row * HH + h] = lo2(acc);
            adst[row * HH + h] = hi2(acc);
        }
    }
}

// ---------------- per-dst-node softmax + weighted aggregation (1 warp/node)
// No-max softmax (|e| bounded ~0.5 by construction). Lane l owns channels
// [8l, 8l+8); one LDG.128 = 8 fp16 per edge per lane; fp32 accumulation.
__global__ __launch_bounds__(256) void k_aggr(const __half* __restrict__ hf,
                                              const float* __restrict__ asrc,
                                              const float* __restrict__ adst,
                                              const float* __restrict__ bias,
                                              float* __restrict__ out, int n) {
    __shared__ float4 wbuf[8][32];
    __shared__ int    sbuf[8][32];
    int wid = threadIdx.x >> 5;
    int lane = threadIdx.x & 31;
    int node = (blockIdx.x * blockDim.x + threadIdx.x) >> 5;
    if (node >= n) return;

    int base = g_rowptr[node];
    int deg = g_rowptr[node + 1] - base;
    int h = lane >> 3;
    const float* wcol = (const float*)&wbuf[wid][0] + h;   // scalar w reads

    float4 ad = *(const float4*)(adst + (size_t)node * 4);

    float d0 = 0.f, d1 = 0.f, d2 = 0.f, d3 = 0.f;
    unsigned long long acc[4] = {0ull, 0ull, 0ull, 0ull};
    const __half* hlane = hf + lane * 8;

    for (int ib = 0; ib < deg; ib += 32) {
        int rem = min(32, deg - ib);
        {
            int sl = 0;
            float w0 = 0.f, w1 = 0.f, w2 = 0.f, w3 = 0.f;
            if (lane < rem) {
                sl = g_csr[base + ib + lane];
                float4 as = *(const float4*)(asrc + (size_t)sl * 4);
                w0 = __expf(lrelu(as.x + ad.x, 0.2f));
                w1 = __expf(lrelu(as.y + ad.y, 0.2f));
                w2 = __expf(lrelu(as.z + ad.z, 0.2f));
                w3 = __expf(lrelu(as.w + ad.w, 0.2f));
                d0 += w0; d1 += w1; d2 += w2; d3 += w3;
            }
            sbuf[wid][lane] = sl;
            wbuf[wid][lane] = make_float4(w0, w1, w2, w3);
        }
        __syncwarp();
        for (int j = 0; j < rem; j++) {
            int s = sbuf[wid][j];                 // LDS broadcast
            float wv = wcol[j * 4];               // scalar LDS (4-addr broadcast)
            unsigned long long w2p = pack2(wv, wv);
            uint4 hv = *(const uint4*)(hlane + (size_t)s * FOUT);  // 8 fp16
            ffma2(acc[0], w2p, h2f2(hv.x));
            ffma2(acc[1], w2p, h2f2(hv.y));
            ffma2(acc[2], w2p, h2f2(hv.z));
            ffma2(acc[3], w2p, h2f2(hv.w));
        }
        __syncwarp();
    }

    #pragma unroll
    for (int o = 16; o; o >>= 1) {
        d0 += __shfl_xor_sync(0xffffffffu, d0, o);
        d1 += __shfl_xor_sync(0xffffffffu, d1, o);
        d2 += __shfl_xor_sync(0xffffffffu, d2, o);
        d3 += __shfl_xor_sync(0xffffffffu, d3, o);
    }
    float i0 = d0 > 0.f ? 0.25f / d0 : 0.f;
    float i1 = d1 > 0.f ? 0.25f / d1 : 0.f;
    float i2 = d2 > 0.f ? 0.25f / d2 : 0.f;
    float i3 = d3 > 0.f ? 0.25f / d3 : 0.f;
    float inv = (h == 0) ? i0 : (h == 1) ? i1 : (h == 2) ? i2 : i3;
    unsigned long long inv2 = pack2(inv, inv);
    #pragma unroll
    for (int j = 0; j < 4; j++) mul2(acc[j], inv2);

    float v[8];
    #pragma unroll
    for (int j = 0; j < 4; j++) { v[2 * j] = lo2(acc[j]); v[2 * j + 1] = hi2(acc[j]); }
    #pragma unroll
    for (int j = 0; j < 8; j++) {
        v[j] += __shfl_xor_sync(0xffffffffu, v[j], 8);
        v[j] += __shfl_xor_sync(0xffffffffu, v[j], 16);
    }

    if (lane < 8) {
        const float4* bp = (const float4*)(bias + lane * 8);
        float4 bA = bp[0], bB = bp[1];
        float4 oA = make_float4(lrelu(v[0] + bA.x, 0.1f), lrelu(v[1] + bA.y, 0.1f),
                                lrelu(v[2] + bA.z, 0.1f), lrelu(v[3] + bA.w, 0.1f));
        float4 oB = make_float4(lrelu(v[4] + bB.x, 0.1f), lrelu(v[5] + bB.y, 0.1f),
                                lrelu(v[6] + bB.z, 0.1f), lrelu(v[7] + bB.w, 0.1f));
        float4* op = (float4*)(out + (size_t)node * CC + lane * 8);
        op[0] = oA;
        op[1] = oB;
    }
}

// ---------------------------------------------------------------------------
extern "C" void kernel_launch(void* const* d_in, const int* in_sizes, int n_in,
                              void* d_out, int out_size) {
    const float* x        = (const float*)d_in[0];
    const int*   ei       = (const int*)d_in[1];
    const float* W1       = (const float*)d_in[2];
    const float* A1       = (const float*)d_in[3];
    const float* att_src1 = (const float*)d_in[4];
    const float* att_dst1 = (const float*)d_in[5];
    const float* b1       = (const float*)d_in[6];
    const float* W2       = (const float*)d_in[7];
    const float* A2       = (const float*)d_in[8];
    const float* att_src2 = (const float*)d_in[9];
    const float* att_dst2 = (const float*)d_in[10];
    const float* b2       = (const float*)d_in[11];
    float* out = (float*)d_out;

    const int n = NN;
    const int eb2 = (EE / 2 + 255) / 256;

    __half* p_h;
    float *p_x2, *p_asrc, *p_adst, *p_vc1, *p_vc2;
    cudaGetSymbolAddress((void**)&p_h, g_h);
    cudaGetSymbolAddress((void**)&p_x2, g_x2);
    cudaGetSymbolAddress((void**)&p_asrc, g_asrc);
    cudaGetSymbolAddress((void**)&p_adst, g_adst);
    cudaGetSymbolAddress((void**)&p_vc1, g_vc1);
    cudaGetSymbolAddress((void**)&p_vc2, g_vc2);

    // lazy side-stream + events (created on the first, non-captured call;
    // fork/join via events is the supported pattern inside stream capture)
    static cudaStream_t s2 = nullptr;
    static cudaEvent_t ev_fork = nullptr, ev_join = nullptr;
    if (!s2) {
        cudaStreamCreateWithFlags(&s2, cudaStreamNonBlocking);
        cudaEventCreateWithFlags(&ev_fork, cudaEventDisableTiming);
        cudaEventCreateWithFlags(&ev_join, cudaEventDisableTiming);
    }

    // #1 prep (detect + combines) on the main stream
    k_prep<<<2, 256>>>(ei, A1, att_src1, att_dst1, A2, att_src2, att_dst2);

    // fork: gemm1 runs on s2 concurrently with the CSR build
    cudaEventRecord(ev_fork, 0);
    cudaStreamWaitEvent(s2, ev_fork, 0);
    k_gemm<128><<<(n + 63) / 64, 256, 0, s2>>>(x, W1, p_h, p_vc1, p_asrc, p_adst, n);
    cudaEventRecord(ev_join, s2);

    // CSR build on the main stream (independent of gemm1)
    k_hist<<<eb2, 256>>>(ei);
    k_blocksum_scan<<<NB2, 256>>>();
    k_writeoff<<<NB2, 256>>>();
    k_scatter<<<eb2, 256>>>(ei);

    // join: aggr1 needs both the CSR and gemm1 results
    cudaStreamWaitEvent(0, ev_join, 0);
    k_aggr<<<(n * 32 + 255) / 256, 256>>>(p_h, p_asrc, p_adst, b1, p_x2, n);

    // layer 2 (serial: each kernel depends on the previous)
    k_gemm<64><<<(n + 63) / 64, 256>>>(p_x2, W2, p_h, p_vc2, p_asrc, p_adst, n);
    k_aggr<<<(n * 32 + 255) / 256, 256>>>(p_h, p_asrc, p_adst, b2, out, n);
}